// round 4
// baseline (speedup 1.0000x reference)
#include <cuda_runtime.h>
#include <cuda_bf16.h>
#include <cstdint>

// ---------------- problem constants ----------------
#define NN 32
#define CCH 128
#define HH 64
#define WW 64
#define NHW_F 131072.0f
#define EPSV 1e-5f

// ---------------- smem layout (byte offsets) ----------------
// W tiles: 128 rows x 256B, stride 272B (17 segs -> LDSM conflict-free)
// T tiles: single 32-row chunk, same stride
#define TSTRIDE 272
#define WHI_OFF 0
#define WLO_OFF 34816              // 128*272
#define THI_OFF 69632
#define TLO_OFF 78336              // +32*272
#define XS_OFF  87040
#define XS_STRIDE 185              // floats
#define SMEM_BYTES (XS_OFF + 32 * XS_STRIDE * 4)   // 110,720 B -> 2 CTAs/SM
#define HALO_N 5760                // 32 ch * 180
#define HALO_IT 23                 // ceil(5760/256)

// ---------------- device scratch ----------------
__device__ float g_y1[NN * CCH * HH * WW];
__device__ unsigned char g_wt[131072];     // 2 blocks x (hi 32KB + lo 32KB), [o][c]
__device__ float g_stats[4 * CCH];
__device__ float g_sc[4 * CCH];

// ---------------- PTX helpers ----------------
__device__ __forceinline__ uint32_t smem_u32(const void* p) {
    uint32_t a;
    asm("{ .reg .u64 t; cvta.to.shared.u64 t, %1; cvt.u32.u64 %0, t; }" : "=r"(a) : "l"(p));
    return a;
}
__device__ __forceinline__ void ldsm_x4(uint32_t* r, uint32_t a) {
    asm volatile("ldmatrix.sync.aligned.m8n8.x4.shared.b16 {%0,%1,%2,%3}, [%4];"
                 : "=r"(r[0]), "=r"(r[1]), "=r"(r[2]), "=r"(r[3]) : "r"(a));
}
__device__ __forceinline__ void ldsmt_x4(uint32_t* r, uint32_t a) {
    asm volatile("ldmatrix.sync.aligned.m8n8.x4.trans.shared.b16 {%0,%1,%2,%3}, [%4];"
                 : "=r"(r[0]), "=r"(r[1]), "=r"(r[2]), "=r"(r[3]) : "r"(a));
}
__device__ __forceinline__ void mma16816(float* d, const uint32_t* a, const uint32_t* b) {
    asm volatile("mma.sync.aligned.m16n8k16.row.col.f32.bf16.bf16.f32 "
                 "{%0,%1,%2,%3}, {%4,%5,%6,%7}, {%8,%9}, {%0,%1,%2,%3};"
                 : "+f"(d[0]), "+f"(d[1]), "+f"(d[2]), "+f"(d[3])
                 : "r"(a[0]), "r"(a[1]), "r"(a[2]), "r"(a[3]), "r"(b[0]), "r"(b[1]));
}

// ---------------- prep: split pw weights to bf16 hi/lo; zero stats ----------------
__global__ void prep_w(const float* __restrict__ pw1, const float* __restrict__ pw2,
                       unsigned char* __restrict__ wt, float* __restrict__ stats) {
    int idx = blockIdx.x * blockDim.x + threadIdx.x;
    if (idx < 4 * CCH) stats[idx] = 0.f;
    if (idx >= 32768) return;
    int blk = idx >> 14;
    int w = idx & 16383;
    float v = (blk ? pw2 : pw1)[w];
    __nv_bfloat16 h = __float2bfloat16(v);
    __nv_bfloat16 l = __float2bfloat16(v - __bfloat162float(h));
    unsigned char* base = wt + (uint32_t)blk * 65536u;
    *(__nv_bfloat16*)(base + (uint32_t)w * 2u) = h;
    *(__nv_bfloat16*)(base + 32768u + (uint32_t)w * 2u) = l;
}

// ---------------- fused relu(+BN) -> dw3x3 -> HMMA pointwise + stats ----------------
template <bool PRE_BN>
__global__ __launch_bounds__(256, 2) void conv_mma(
    const float* __restrict__ in, const float* __restrict__ dww,
    const unsigned char* __restrict__ wt,
    const float* __restrict__ prescale, const float* __restrict__ preshift,
    float* __restrict__ out, float* __restrict__ osum, float* __restrict__ osq)
{
    extern __shared__ char smb[];
    const uint32_t base32 = smem_u32(smb);

    const int tid = threadIdx.x;
    const int wid = tid >> 5;
    const int lane = tid & 31;
    const int bx = blockIdx.x;
    const int n = bx >> 5;
    const int tile = bx & 31;
    const int th0 = (tile >> 2) * 8;
    const int tw0 = (tile & 3) * 16;

    float* xs = (float*)(smb + XS_OFF);

    // ---- halo prefetch into registers (chunk ch) ----
    float hreg[HALO_IT];
    {
        const int c0 = 0;
        #pragma unroll
        for (int u = 0; u < HALO_IT; u++) {
            int idx = tid + u * 256;
            float v = 0.f;
            if (idx < HALO_N) {
                int c = idx / 180;
                int rem = idx - c * 180;
                int r = rem / 18;
                int col = rem - r * 18;
                int gh = th0 - 1 + r, gw = tw0 - 1 + col;
                if ((unsigned)gh < (unsigned)HH && (unsigned)gw < (unsigned)WW) {
                    v = in[((n * CCH + c0 + c) * HH + gh) * WW + gw];
                    if (PRE_BN) v = fmaf(v, prescale[c0 + c], preshift[c0 + c]);
                    v = fmaxf(v, 0.f);
                }
            }
            hreg[u] = v;
        }
    }

    // ---- W copy (overlaps with halo LDG latency) ----
    {
        const uint32_t* whi = (const uint32_t*)wt;
        const uint32_t* wlo = whi + 8192;
        #pragma unroll 4
        for (int i = tid; i < 8192; i += 256) {
            int o = i >> 6, cp = i & 63;
            uint32_t off = (uint32_t)o * TSTRIDE + (uint32_t)cp * 4u;
            *(uint32_t*)(smb + WHI_OFF + off) = whi[i];
            *(uint32_t*)(smb + WLO_OFF + off) = wlo[i];
        }
    }

    // GEMM per-warp tiling: 32(o) x 64(px)
    const int o0 = (wid & 3) * 32;
    const int p0 = (wid >> 2) * 64;
    const uint32_t aRow = (uint32_t)(o0 + (lane & 15)) * TSTRIDE + (uint32_t)(lane >> 4) * 16u;
    const uint32_t bRow = (uint32_t)(lane & 15) * TSTRIDE + (uint32_t)(p0 + (lane >> 4) * 8) * 2u;
    const uint32_t aHi0 = base32 + WHI_OFF + aRow;
    const uint32_t aLo0 = base32 + WLO_OFF + aRow;
    const uint32_t bHi0 = base32 + THI_OFF + bRow;
    const uint32_t bLo0 = base32 + TLO_OFF + bRow;

    float d[2][8][4];
    #pragma unroll
    for (int i = 0; i < 2; i++)
        #pragma unroll
        for (int j = 0; j < 8; j++)
            #pragma unroll
            for (int r = 0; r < 4; r++) d[i][j][r] = 0.f;

    for (int ch = 0; ch < 4; ch++) {
        const int c0 = ch * 32;

        // ---- store prefetched halo to smem ----
        #pragma unroll
        for (int u = 0; u < HALO_IT; u++) {
            int idx = tid + u * 256;
            if (idx < HALO_N) {
                int c = idx / 180;
                int rem = idx - c * 180;
                xs[c * XS_STRIDE + rem] = hreg[u];
            }
        }

        // ---- prefetch next chunk's halo into registers ----
        if (ch < 3) {
            const int c0n = c0 + 32;
            #pragma unroll
            for (int u = 0; u < HALO_IT; u++) {
                int idx = tid + u * 256;
                float v = 0.f;
                if (idx < HALO_N) {
                    int c = idx / 180;
                    int rem = idx - c * 180;
                    int r = rem / 18;
                    int col = rem - r * 18;
                    int gh = th0 - 1 + r, gw = tw0 - 1 + col;
                    if ((unsigned)gh < (unsigned)HH && (unsigned)gw < (unsigned)WW) {
                        v = in[((n * CCH + c0n + c) * HH + gh) * WW + gw];
                        if (PRE_BN) v = fmaf(v, prescale[c0n + c], preshift[c0n + c]);
                        v = fmaxf(v, 0.f);
                    }
                }
                hreg[u] = v;
            }
        }

        __syncthreads();   // xs ready; all warps past MMA(ch-1) -> T writable

        // ---- depthwise 3x3, bf16 hi/lo split into single-chunk T tile ----
        {
            const int cl = tid >> 3;          // local channel 0..31
            const int m = tid & 7;
            const float* wp = dww + (c0 + cl) * 9;
            float w0 = wp[0], w1 = wp[1], w2 = wp[2], w3 = wp[3], w4 = wp[4],
                  w5 = wp[5], w6 = wp[6], w7 = wp[7], w8 = wp[8];
            const float* xb = xs + cl * XS_STRIDE;
            #pragma unroll
            for (int k = 0; k < 8; k++) {
                int pp = m + 8 * k;           // pixel pair index
                int px = 2 * pp;
                int ph = px >> 4, pwx = px & 15;
                const float* p = xb + ph * 18 + pwx;
                float s0 = w0 * p[0]  + w1 * p[1]  + w2 * p[2]
                         + w3 * p[18] + w4 * p[19] + w5 * p[20]
                         + w6 * p[36] + w7 * p[37] + w8 * p[38];
                float s1 = w0 * p[1]  + w1 * p[2]  + w2 * p[3]
                         + w3 * p[19] + w4 * p[20] + w5 * p[21]
                         + w6 * p[37] + w7 * p[38] + w8 * p[39];
                __nv_bfloat16 h0 = __float2bfloat16(s0);
                __nv_bfloat16 h1 = __float2bfloat16(s1);
                __nv_bfloat16 l0 = __float2bfloat16(s0 - __bfloat162float(h0));
                __nv_bfloat16 l1 = __float2bfloat16(s1 - __bfloat162float(h1));
                uint32_t hw = (uint32_t)__bfloat16_as_ushort(h0)
                            | ((uint32_t)__bfloat16_as_ushort(h1) << 16);
                uint32_t lw = (uint32_t)__bfloat16_as_ushort(l0)
                            | ((uint32_t)__bfloat16_as_ushort(l1) << 16);
                uint32_t off = (uint32_t)cl * TSTRIDE + (uint32_t)pp * 4u;
                *(uint32_t*)(smb + THI_OFF + off) = hw;
                *(uint32_t*)(smb + TLO_OFF + off) = lw;
            }
        }
        __syncthreads();   // T(ch) ready

        // ---- MMA for this chunk: 2 k-steps, hi/lo 3-product ----
        {
            const uint32_t aOff = (uint32_t)ch * 64u;
            #pragma unroll
            for (int kk2 = 0; kk2 < 2; kk2++) {
                const uint32_t ao = aOff + (uint32_t)kk2 * 32u;
                const uint32_t bo = (uint32_t)kk2 * (16u * TSTRIDE);
                uint32_t ah[2][4], al[2][4];
                ldsm_x4(ah[0], aHi0 + ao);
                ldsm_x4(ah[1], aHi0 + ao + 16u * TSTRIDE);
                ldsm_x4(al[0], aLo0 + ao);
                ldsm_x4(al[1], aLo0 + ao + 16u * TSTRIDE);
                #pragma unroll
                for (int g = 0; g < 4; g++) {
                    uint32_t bh[4], bl[4];
                    ldsmt_x4(bh, bHi0 + bo + (uint32_t)g * 32u);
                    ldsmt_x4(bl, bLo0 + bo + (uint32_t)g * 32u);
                    #pragma unroll
                    for (int i = 0; i < 2; i++) {
                        #pragma unroll
                        for (int h = 0; h < 2; h++) {
                            float* dd = d[i][g * 2 + h];
                            mma16816(dd, ah[i], &bh[h * 2]);
                            mma16816(dd, ah[i], &bl[h * 2]);
                            mma16816(dd, al[i], &bh[h * 2]);
                        }
                    }
                }
            }
        }
    }

    // ---- epilogue: write raw output + per-channel stats ----
    __syncthreads();                          // xs free for reduction reuse
    const int grp = lane >> 2, tg = lane & 3;
    float* redS = xs;                         // 256 floats
    float* redQ = xs + 256;
    #pragma unroll
    for (int i = 0; i < 2; i++) {
        #pragma unroll
        for (int rh = 0; rh < 2; rh++) {
            int o = o0 + i * 16 + grp + rh * 8;
            float s = 0.f, q = 0.f;
            #pragma unroll
            for (int j = 0; j < 8; j++) {
                int px = p0 + j * 8 + tg * 2;
                float v0 = d[i][j][rh * 2], v1 = d[i][j][rh * 2 + 1];
                *(float2*)(out + ((size_t)(n * CCH + o) * HH + th0 + (px >> 4)) * WW
                                 + tw0 + (px & 15)) = make_float2(v0, v1);
                s += v0 + v1;
                q = fmaf(v0, v0, fmaf(v1, v1, q));
            }
            s += __shfl_xor_sync(0xffffffffu, s, 1);
            s += __shfl_xor_sync(0xffffffffu, s, 2);
            q += __shfl_xor_sync(0xffffffffu, q, 1);
            q += __shfl_xor_sync(0xffffffffu, q, 2);
            if (tg == 0) {
                redS[o * 2 + (wid >> 2)] = s;
                redQ[o * 2 + (wid >> 2)] = q;
            }
        }
    }
    __syncthreads();
    if (tid < CCH) {
        atomicAdd(&osum[tid], redS[tid * 2] + redS[tid * 2 + 1]);
        atomicAdd(&osq[tid], redQ[tid * 2] + redQ[tid * 2 + 1]);
    }
}

// ---------------- BN helpers ----------------
__global__ void bn_finalize(const float* __restrict__ sum, const float* __restrict__ sq,
                            const float* __restrict__ gamma, const float* __restrict__ beta,
                            float* __restrict__ scale, float* __restrict__ shift) {
    int c = threadIdx.x;
    float inv = 1.0f / NHW_F;
    float m = sum[c] * inv;
    float v = sq[c] * inv - m * m;
    float sc = gamma[c] * rsqrtf(v + EPSV);
    scale[c] = sc;
    shift[c] = beta[c] - m * sc;
}

__global__ void bn_apply(float* __restrict__ y, const float* __restrict__ scale,
                         const float* __restrict__ shift) {
    const int total4 = (NN * CCH * HH * WW) / 4;
    float4* p = (float4*)y;
    for (int i = blockIdx.x * blockDim.x + threadIdx.x; i < total4;
         i += gridDim.x * blockDim.x) {
        int c = (i >> 10) & (CCH - 1);
        float s = scale[c], t = shift[c];
        float4 v = p[i];
        v.x = fmaf(v.x, s, t); v.y = fmaf(v.y, s, t);
        v.z = fmaf(v.z, s, t); v.w = fmaf(v.w, s, t);
        p[i] = v;
    }
}

// ---------------- launch ----------------
extern "C" void kernel_launch(void* const* d_in, const int* in_sizes, int n_in,
                              void* d_out, int out_size) {
    const float* x      = (const float*)d_in[0];
    const float* dw1_w  = (const float*)d_in[1];
    const float* pw1_w  = (const float*)d_in[2];
    const float* gamma1 = (const float*)d_in[3];
    const float* beta1  = (const float*)d_in[4];
    const float* dw2_w  = (const float*)d_in[5];
    const float* pw2_w  = (const float*)d_in[6];
    const float* gamma2 = (const float*)d_in[7];
    const float* beta2  = (const float*)d_in[8];
    float* out = (float*)d_out;

    float *y1, *stats, *sc;
    unsigned char* wt;
    cudaGetSymbolAddress((void**)&y1, g_y1);
    cudaGetSymbolAddress((void**)&stats, g_stats);
    cudaGetSymbolAddress((void**)&sc, g_sc);
    cudaGetSymbolAddress((void**)&wt, g_wt);

    cudaFuncSetAttribute((const void*)conv_mma<false>,
                         cudaFuncAttributeMaxDynamicSharedMemorySize, SMEM_BYTES);
    cudaFuncSetAttribute((const void*)conv_mma<true>,
                         cudaFuncAttributeMaxDynamicSharedMemorySize, SMEM_BYTES);
    cudaFuncSetAttribute((const void*)conv_mma<false>,
                         cudaFuncAttributePreferredSharedMemoryCarveout, 100);
    cudaFuncSetAttribute((const void*)conv_mma<true>,
                         cudaFuncAttributePreferredSharedMemoryCarveout, 100);

    prep_w<<<64, 512>>>(pw1_w, pw2_w, wt, stats);

    conv_mma<false><<<1024, 256, SMEM_BYTES>>>(x, dw1_w, wt, nullptr, nullptr,
                                               y1, stats, stats + CCH);
    bn_finalize<<<1, CCH>>>(stats, stats + CCH, gamma1, beta1, sc, sc + CCH);

    conv_mma<true><<<1024, 256, SMEM_BYTES>>>(y1, dw2_w, wt + 65536, sc, sc + CCH,
                                              out, stats + 2 * CCH, stats + 3 * CCH);
    bn_finalize<<<1, CCH>>>(stats + 2 * CCH, stats + 3 * CCH, gamma2, beta2,
                            sc + 2 * CCH, sc + 3 * CCH);

    bn_apply<<<2048, 256>>>(out, sc + 2 * CCH, sc + 3 * CCH);
}

// round 6
// speedup vs baseline: 2.1188x; 2.1188x over previous
#include <cuda_runtime.h>
#include <cuda_bf16.h>
#include <cstdint>

// ---------------- problem constants ----------------
#define NN 32
#define CCH 128
#define HH 64
#define WW 64
#define NHW_F 131072.0f
#define EPSV 1e-5f

// ---------------- smem layout (byte offsets) ----------------
#define TSTRIDE 272                 // 17x16B segs -> LDSM conflict-free
#define WHI_OFF 0
#define WLO_OFF 34816               // 128*272
#define THI_OFF 69632               // 32*272 = 8704
#define TLO_OFF 78336
#define XS0_OFF 87040
#define XS_STRIDE 185               // floats
#define XSBUF_BYTES (32 * XS_STRIDE * 4)    // 23680
#define XS1_OFF (XS0_OFF + XSBUF_BYTES)     // 110720
#define RED_OFF (XS1_OFF + XSBUF_BYTES)     // 134400
#define SMEM_BYTES (RED_OFF + 4096)         // 138496
#define HALO_N 5760                 // 32 ch * 180

// ---------------- device scratch ----------------
__device__ float g_y1[NN * CCH * HH * WW];
__device__ unsigned char g_wt[131072];      // 2 blocks x (hi 32KB + lo 32KB), [o][c]
__device__ float g_stats[4 * CCH];
__device__ float g_sc[4 * CCH];

// ---------------- PTX helpers ----------------
__device__ __forceinline__ uint32_t smem_u32(const void* p) {
    uint32_t a;
    asm("{ .reg .u64 t; cvta.to.shared.u64 t, %1; cvt.u32.u64 %0, t; }" : "=r"(a) : "l"(p));
    return a;
}
__device__ __forceinline__ void ldsm_x4(uint32_t* r, uint32_t a) {
    asm volatile("ldmatrix.sync.aligned.m8n8.x4.shared.b16 {%0,%1,%2,%3}, [%4];"
                 : "=r"(r[0]), "=r"(r[1]), "=r"(r[2]), "=r"(r[3]) : "r"(a));
}
__device__ __forceinline__ void ldsmt_x4(uint32_t* r, uint32_t a) {
    asm volatile("ldmatrix.sync.aligned.m8n8.x4.trans.shared.b16 {%0,%1,%2,%3}, [%4];"
                 : "=r"(r[0]), "=r"(r[1]), "=r"(r[2]), "=r"(r[3]) : "r"(a));
}
__device__ __forceinline__ void mma16816(float* d, const uint32_t* a, const uint32_t* b) {
    asm volatile("mma.sync.aligned.m16n8k16.row.col.f32.bf16.bf16.f32 "
                 "{%0,%1,%2,%3}, {%4,%5,%6,%7}, {%8,%9}, {%0,%1,%2,%3};"
                 : "+f"(d[0]), "+f"(d[1]), "+f"(d[2]), "+f"(d[3])
                 : "r"(a[0]), "r"(a[1]), "r"(a[2]), "r"(a[3]), "r"(b[0]), "r"(b[1]));
}
__device__ __forceinline__ void cp_async4(uint32_t dst, const void* src, uint32_t srcsz) {
    asm volatile("cp.async.ca.shared.global [%0], [%1], 4, %2;"
                 :: "r"(dst), "l"(src), "r"(srcsz) : "memory");
}
#define CP_COMMIT() asm volatile("cp.async.commit_group;" ::: "memory")
#define CP_WAIT1()  asm volatile("cp.async.wait_group 1;" ::: "memory")
#define CP_WAIT0()  asm volatile("cp.async.wait_group 0;" ::: "memory")

// ---------------- prep: split pw weights to bf16 hi/lo; zero stats ----------------
__global__ void prep_w(const float* __restrict__ pw1, const float* __restrict__ pw2,
                       unsigned char* __restrict__ wt, float* __restrict__ stats) {
    int idx = blockIdx.x * blockDim.x + threadIdx.x;
    if (idx < 4 * CCH) stats[idx] = 0.f;
    if (idx >= 32768) return;
    int blk = idx >> 14;
    int w = idx & 16383;
    float v = (blk ? pw2 : pw1)[w];
    __nv_bfloat16 h = __float2bfloat16(v);
    __nv_bfloat16 l = __float2bfloat16(v - __bfloat162float(h));
    unsigned char* base = wt + (uint32_t)blk * 65536u;
    *(__nv_bfloat16*)(base + (uint32_t)w * 2u) = h;
    *(__nv_bfloat16*)(base + 32768u + (uint32_t)w * 2u) = l;
}

// ---------------- fused relu(+BN) -> dw3x3 -> HMMA pointwise + stats ----------------
// 512 CTAs x 512 threads; each CTA: 2 tiles x 4 chunk-stages, cp.async pipelined.
template <bool PRE_BN>
__global__ __launch_bounds__(512, 1) void conv_mma(
    const float* __restrict__ in, const float* __restrict__ dww,
    const unsigned char* __restrict__ wt,
    const float* __restrict__ prescale, const float* __restrict__ preshift,
    float* __restrict__ out, float* __restrict__ osum, float* __restrict__ osq)
{
    extern __shared__ char smb[];
    const uint32_t base32 = smem_u32(smb);

    const int tid = threadIdx.x;
    const int wid = tid >> 5;
    const int lane = tid & 31;
    const int n = blockIdx.x >> 4;
    const int sub = blockIdx.x & 15;

    // ---- halo issue for stage s (tile = sub*2 + (s>>2), chunk = s&3) ----
    auto issue_halo = [&](int s) {
        const int tile = sub * 2 + (s >> 2);
        const int th0 = (tile >> 2) * 8;
        const int tw0 = (tile & 3) * 16;
        const int c0 = (s & 3) * 32;
        const uint32_t xsb = base32 + ((s & 1) ? XS1_OFF : XS0_OFF);
        #pragma unroll
        for (int u = 0; u < 12; u++) {
            int idx = tid + u * 512;
            if (idx < HALO_N) {
                int c = idx / 180;
                int rem = idx - c * 180;
                int r = rem / 18;
                int col = rem - r * 18;
                int gh = th0 - 1 + r, gw = tw0 - 1 + col;
                bool ok = (unsigned)gh < (unsigned)HH && (unsigned)gw < (unsigned)WW;
                const float* src = ok ? in + ((n * CCH + c0 + c) * HH + gh) * WW + gw : in;
                cp_async4(xsb + (uint32_t)(c * XS_STRIDE + rem) * 4u, src, ok ? 4u : 0u);
            }
        }
        CP_COMMIT();
    };

    issue_halo(0);

    // ---- W copy into padded smem (overlaps stage-0 cp.async) ----
    {
        const uint32_t* whi = (const uint32_t*)wt;
        const uint32_t* wlo = whi + 8192;
        #pragma unroll 4
        for (int i = tid; i < 8192; i += 512) {
            int o = i >> 6, cp = i & 63;
            uint32_t off = (uint32_t)o * TSTRIDE + (uint32_t)cp * 4u;
            *(uint32_t*)(smb + WHI_OFF + off) = whi[i];
            *(uint32_t*)(smb + WLO_OFF + off) = wlo[i];
        }
    }

    // GEMM per-warp tiling: 32(o) x 32(px)
    const int o0 = (wid & 3) * 32;
    const int p0 = (wid >> 2) * 32;
    const uint32_t aRow = (uint32_t)(o0 + (lane & 15)) * TSTRIDE + (uint32_t)(lane >> 4) * 16u;
    const uint32_t bRow = (uint32_t)(lane & 15) * TSTRIDE + (uint32_t)(p0 + (lane >> 4) * 8) * 2u;
    const uint32_t aHi0 = base32 + WHI_OFF + aRow;
    const uint32_t aLo0 = base32 + WLO_OFF + aRow;
    const uint32_t bHi0 = base32 + THI_OFF + bRow;
    const uint32_t bLo0 = base32 + TLO_OFF + bRow;

    float d[2][4][4];
    #pragma unroll
    for (int i = 0; i < 2; i++)
        #pragma unroll
        for (int j = 0; j < 4; j++)
            #pragma unroll
            for (int r = 0; r < 4; r++) d[i][j][r] = 0.f;

    for (int s = 0; s < 8; s++) {
        const int tile = sub * 2 + (s >> 2);
        const int th0 = (tile >> 2) * 8;
        const int tw0 = (tile & 3) * 16;
        const int ch = s & 3;
        const int c0 = ch * 32;
        float* xs = (float*)(smb + ((s & 1) ? XS1_OFF : XS0_OFF));

        if (s < 7) issue_halo(s + 1);
        if (s < 7) { CP_WAIT1(); } else { CP_WAIT0(); }
        __syncthreads();   // stage-s halo arrived; all warps past MMA(s-1)

        // ---- warp-local in-place transform: relu(+BN), border zeroing ----
        {
            const bool interior = (th0 > 0) && (th0 < 56) && (tw0 > 0) && (tw0 < 48);
            const int cA = 2 * wid;        // this warp's two channels
            float scv[2], shv[2];
            if (PRE_BN) {
                scv[0] = prescale[c0 + cA];     scv[1] = prescale[c0 + cA + 1];
                shv[0] = preshift[c0 + cA];     shv[1] = preshift[c0 + cA + 1];
            }
            #pragma unroll
            for (int u = 0; u < 12; u++) {
                int e = lane + u * 32;
                if (e < 360) {
                    int cl = e >= 180;
                    int rem = e - cl * 180;
                    float* p = xs + (cA + cl) * XS_STRIDE + rem;
                    float v = *p;
                    if (PRE_BN) v = fmaf(v, scv[cl], shv[cl]);
                    v = fmaxf(v, 0.f);
                    if (!interior) {
                        int r = rem / 18, col = rem - r * 18;
                        int gh = th0 - 1 + r, gw = tw0 - 1 + col;
                        if ((unsigned)gh >= (unsigned)HH || (unsigned)gw >= (unsigned)WW)
                            v = 0.f;
                    }
                    *p = v;
                }
            }
            __syncwarp();
        }

        // ---- depthwise 3x3, bf16 hi/lo split into T tile ----
        {
            const int cl = tid >> 4;       // local channel 0..31
            const int m = tid & 15;
            const float* wp = dww + (c0 + cl) * 9;
            float w0 = wp[0], w1 = wp[1], w2 = wp[2], w3 = wp[3], w4 = wp[4],
                  w5 = wp[5], w6 = wp[6], w7 = wp[7], w8 = wp[8];
            const float* xb = xs + cl * XS_STRIDE;
            #pragma unroll
            for (int k = 0; k < 4; k++) {
                int px = 2 * m + 32 * k;
                int ph = px >> 4, pwx = px & 15;
                const float* p = xb + ph * 18 + pwx;
                float s0 = w0 * p[0]  + w1 * p[1]  + w2 * p[2]
                         + w3 * p[18] + w4 * p[19] + w5 * p[20]
                         + w6 * p[36] + w7 * p[37] + w8 * p[38];
                float s1 = w0 * p[1]  + w1 * p[2]  + w2 * p[3]
                         + w3 * p[19] + w4 * p[20] + w5 * p[21]
                         + w6 * p[37] + w7 * p[38] + w8 * p[39];
                __nv_bfloat16 h0 = __float2bfloat16(s0);
                __nv_bfloat16 h1 = __float2bfloat16(s1);
                __nv_bfloat16 l0 = __float2bfloat16(s0 - __bfloat162float(h0));
                __nv_bfloat16 l1 = __float2bfloat16(s1 - __bfloat162float(h1));
                uint32_t hw = (uint32_t)__bfloat16_as_ushort(h0)
                            | ((uint32_t)__bfloat16_as_ushort(h1) << 16);
                uint32_t lw = (uint32_t)__bfloat16_as_ushort(l0)
                            | ((uint32_t)__bfloat16_as_ushort(l1) << 16);
                uint32_t off = (uint32_t)cl * TSTRIDE + (uint32_t)px * 2u;
                *(uint32_t*)(smb + THI_OFF + off) = hw;
                *(uint32_t*)(smb + TLO_OFF + off) = lw;
            }
        }
        __syncthreads();   // T(ch) ready

        // ---- MMA for this chunk: 2 k-steps, hi/lo 3-product ----
        #pragma unroll
        for (int kk2 = 0; kk2 < 2; kk2++) {
            const uint32_t ao = (uint32_t)(ch * 2 + kk2) * 32u;
            const uint32_t bo = (uint32_t)kk2 * (16u * TSTRIDE);
            uint32_t ah[2][4], al[2][4], bh[2][4], bl[2][4];
            ldsm_x4(ah[0], aHi0 + ao);
            ldsm_x4(ah[1], aHi0 + ao + 16u * TSTRIDE);
            ldsm_x4(al[0], aLo0 + ao);
            ldsm_x4(al[1], aLo0 + ao + 16u * TSTRIDE);
            ldsmt_x4(bh[0], bHi0 + bo);
            ldsmt_x4(bh[1], bHi0 + bo + 32u);
            ldsmt_x4(bl[0], bLo0 + bo);
            ldsmt_x4(bl[1], bLo0 + bo + 32u);
            #pragma unroll
            for (int i = 0; i < 2; i++) {
                #pragma unroll
                for (int j = 0; j < 4; j++) {
                    const uint32_t* bhf = &bh[j >> 1][(j & 1) * 2];
                    const uint32_t* blf = &bl[j >> 1][(j & 1) * 2];
                    mma16816(d[i][j], ah[i], bhf);
                    mma16816(d[i][j], ah[i], blf);
                    mma16816(d[i][j], al[i], bhf);
                }
            }
        }

        // ---- epilogue after last chunk of the tile ----
        if (ch == 3) {
            const int grp = lane >> 2, tg = lane & 3;
            float* redS = (float*)(smb + RED_OFF);       // 512 floats
            float* redQ = redS + 512;
            #pragma unroll
            for (int i = 0; i < 2; i++) {
                #pragma unroll
                for (int rh = 0; rh < 2; rh++) {
                    int o = o0 + i * 16 + grp + rh * 8;
                    float sv = 0.f, qv = 0.f;
                    #pragma unroll
                    for (int j = 0; j < 4; j++) {
                        int px = p0 + j * 8 + tg * 2;
                        float v0 = d[i][j][rh * 2], v1 = d[i][j][rh * 2 + 1];
                        *(float2*)(out + ((size_t)(n * CCH + o) * HH + th0 + (px >> 4)) * WW
                                         + tw0 + (px & 15)) = make_float2(v0, v1);
                        sv += v0 + v1;
                        qv = fmaf(v0, v0, fmaf(v1, v1, qv));
                    }
                    sv += __shfl_xor_sync(0xffffffffu, sv, 1);
                    sv += __shfl_xor_sync(0xffffffffu, sv, 2);
                    qv += __shfl_xor_sync(0xffffffffu, qv, 1);
                    qv += __shfl_xor_sync(0xffffffffu, qv, 2);
                    if (tg == 0) {
                        redS[o * 4 + (wid >> 2)] = sv;
                        redQ[o * 4 + (wid >> 2)] = qv;
                    }
                }
            }
            // full accumulator reset (only correct place to reset)
            #pragma unroll
            for (int i = 0; i < 2; i++)
                #pragma unroll
                for (int j = 0; j < 4; j++)
                    #pragma unroll
                    for (int r = 0; r < 4; r++) d[i][j][r] = 0.f;
            __syncthreads();
            if (tid < CCH) {
                atomicAdd(&osum[tid], redS[tid * 4] + redS[tid * 4 + 1]
                                    + redS[tid * 4 + 2] + redS[tid * 4 + 3]);
                atomicAdd(&osq[tid], redQ[tid * 4] + redQ[tid * 4 + 1]
                                   + redQ[tid * 4 + 2] + redQ[tid * 4 + 3]);
            }
        }
    }
}

// ---------------- BN helpers ----------------
__global__ void bn_finalize(const float* __restrict__ sum, const float* __restrict__ sq,
                            const float* __restrict__ gamma, const float* __restrict__ beta,
                            float* __restrict__ scale, float* __restrict__ shift) {
    int c = threadIdx.x;
    float inv = 1.0f / NHW_F;
    float m = sum[c] * inv;
    float v = sq[c] * inv - m * m;
    float sc = gamma[c] * rsqrtf(v + EPSV);
    scale[c] = sc;
    shift[c] = beta[c] - m * sc;
}

__global__ void bn_apply(float* __restrict__ y, const float* __restrict__ scale,
                         const float* __restrict__ shift) {
    const int total4 = (NN * CCH * HH * WW) / 4;
    float4* p = (float4*)y;
    for (int i = blockIdx.x * blockDim.x + threadIdx.x; i < total4;
         i += gridDim.x * blockDim.x) {
        int c = (i >> 10) & (CCH - 1);
        float s = scale[c], t = shift[c];
        float4 v = p[i];
        v.x = fmaf(v.x, s, t); v.y = fmaf(v.y, s, t);
        v.z = fmaf(v.z, s, t); v.w = fmaf(v.w, s, t);
        p[i] = v;
    }
}

// ---------------- launch ----------------
extern "C" void kernel_launch(void* const* d_in, const int* in_sizes, int n_in,
                              void* d_out, int out_size) {
    const float* x      = (const float*)d_in[0];
    const float* dw1_w  = (const float*)d_in[1];
    const float* pw1_w  = (const float*)d_in[2];
    const float* gamma1 = (const float*)d_in[3];
    const float* beta1  = (const float*)d_in[4];
    const float* dw2_w  = (const float*)d_in[5];
    const float* pw2_w  = (const float*)d_in[6];
    const float* gamma2 = (const float*)d_in[7];
    const float* beta2  = (const float*)d_in[8];
    float* out = (float*)d_out;

    float *y1, *stats, *sc;
    unsigned char* wt;
    cudaGetSymbolAddress((void**)&y1, g_y1);
    cudaGetSymbolAddress((void**)&stats, g_stats);
    cudaGetSymbolAddress((void**)&sc, g_sc);
    cudaGetSymbolAddress((void**)&wt, g_wt);

    cudaFuncSetAttribute((const void*)conv_mma<false>,
                         cudaFuncAttributeMaxDynamicSharedMemorySize, SMEM_BYTES);
    cudaFuncSetAttribute((const void*)conv_mma<true>,
                         cudaFuncAttributeMaxDynamicSharedMemorySize, SMEM_BYTES);

    prep_w<<<64, 512>>>(pw1_w, pw2_w, wt, stats);

    conv_mma<false><<<512, 512, SMEM_BYTES>>>(x, dw1_w, wt, nullptr, nullptr,
                                              y1, stats, stats + CCH);
    bn_finalize<<<1, CCH>>>(stats, stats + CCH, gamma1, beta1, sc, sc + CCH);

    conv_mma<true><<<512, 512, SMEM_BYTES>>>(y1, dw2_w, wt + 65536, sc, sc + CCH,
                                             out, stats + 2 * CCH, stats + 3 * CCH);
    bn_finalize<<<1, CCH>>>(stats + 2 * CCH, stats + 3 * CCH, gamma2, beta2,
                            sc + 2 * CCH, sc + 3 * CCH);

    bn_apply<<<2048, 256>>>(out, sc + 2 * CCH, sc + 3 * CCH);
}

// round 7
// speedup vs baseline: 2.2418x; 1.0580x over previous
#include <cuda_runtime.h>
#include <cuda_bf16.h>
#include <cstdint>

// ---------------- problem constants ----------------
#define NN 32
#define CCH 128
#define HH 64
#define WW 64
#define NHW_F 131072.0f
#define EPSV 1e-5f

// ---------------- smem layout (byte offsets) ----------------
#define TSTRIDE 272                 // 17x16B segs -> LDSM conflict-free
#define WHI_OFF 0
#define WLO_OFF 34816               // 128*272
#define THI_OFF 69632               // 32*272 = 8704
#define TLO_OFF 78336
#define XS0_OFF 87040
// XS: 32 channels x 10 rows x 24 floats (halo col h at offset h+3, cols 1..16 16B-aligned)
#define XROW 24
#define XCH  240
#define XSBUF_BYTES (32 * XCH * 4)          // 30720
#define XS1_OFF (XS0_OFF + XSBUF_BYTES)     // 117760
#define RED_OFF (XS1_OFF + XSBUF_BYTES)     // 148480
#define SMEM_BYTES (RED_OFF + 4096)         // 152576

// ---------------- device scratch ----------------
__device__ float g_y1[NN * CCH * HH * WW];
__device__ unsigned char g_wt[131072];      // 2 blocks x (hi 32KB + lo 32KB), [o][c]
__device__ float g_stats[4 * CCH];
__device__ float g_sc[4 * CCH];

// ---------------- PTX helpers ----------------
__device__ __forceinline__ uint32_t smem_u32(const void* p) {
    uint32_t a;
    asm("{ .reg .u64 t; cvta.to.shared.u64 t, %1; cvt.u32.u64 %0, t; }" : "=r"(a) : "l"(p));
    return a;
}
__device__ __forceinline__ void ldsm_x4(uint32_t* r, uint32_t a) {
    asm volatile("ldmatrix.sync.aligned.m8n8.x4.shared.b16 {%0,%1,%2,%3}, [%4];"
                 : "=r"(r[0]), "=r"(r[1]), "=r"(r[2]), "=r"(r[3]) : "r"(a));
}
__device__ __forceinline__ void ldsmt_x4(uint32_t* r, uint32_t a) {
    asm volatile("ldmatrix.sync.aligned.m8n8.x4.trans.shared.b16 {%0,%1,%2,%3}, [%4];"
                 : "=r"(r[0]), "=r"(r[1]), "=r"(r[2]), "=r"(r[3]) : "r"(a));
}
__device__ __forceinline__ void mma16816(float* d, const uint32_t* a, const uint32_t* b) {
    asm volatile("mma.sync.aligned.m16n8k16.row.col.f32.bf16.bf16.f32 "
                 "{%0,%1,%2,%3}, {%4,%5,%6,%7}, {%8,%9}, {%0,%1,%2,%3};"
                 : "+f"(d[0]), "+f"(d[1]), "+f"(d[2]), "+f"(d[3])
                 : "r"(a[0]), "r"(a[1]), "r"(a[2]), "r"(a[3]), "r"(b[0]), "r"(b[1]));
}
__device__ __forceinline__ void cp_async4(uint32_t dst, const void* src, uint32_t srcsz) {
    asm volatile("cp.async.ca.shared.global [%0], [%1], 4, %2;"
                 :: "r"(dst), "l"(src), "r"(srcsz) : "memory");
}
__device__ __forceinline__ void cp_async16(uint32_t dst, const void* src, uint32_t srcsz) {
    asm volatile("cp.async.cg.shared.global [%0], [%1], 16, %2;"
                 :: "r"(dst), "l"(src), "r"(srcsz) : "memory");
}
#define CP_COMMIT() asm volatile("cp.async.commit_group;" ::: "memory")
#define CP_WAIT1()  asm volatile("cp.async.wait_group 1;" ::: "memory")
#define CP_WAIT0()  asm volatile("cp.async.wait_group 0;" ::: "memory")

// ---------------- prep: split pw weights to bf16 hi/lo; zero stats ----------------
__global__ void prep_w(const float* __restrict__ pw1, const float* __restrict__ pw2,
                       unsigned char* __restrict__ wt, float* __restrict__ stats) {
    int idx = blockIdx.x * blockDim.x + threadIdx.x;
    if (idx < 4 * CCH) stats[idx] = 0.f;
    if (idx >= 32768) return;
    int blk = idx >> 14;
    int w = idx & 16383;
    float v = (blk ? pw2 : pw1)[w];
    __nv_bfloat16 h = __float2bfloat16(v);
    __nv_bfloat16 l = __float2bfloat16(v - __bfloat162float(h));
    unsigned char* base = wt + (uint32_t)blk * 65536u;
    *(__nv_bfloat16*)(base + (uint32_t)w * 2u) = h;
    *(__nv_bfloat16*)(base + 32768u + (uint32_t)w * 2u) = l;
}

// ---------------- fused relu(+BN) -> dw3x3 -> HMMA pointwise + stats ----------------
// 512 CTAs x 512 threads; each CTA: 2 tiles x 4 chunk-stages, cp.async pipelined.
template <bool PRE_BN>
__global__ __launch_bounds__(512, 1) void conv_mma(
    const float* __restrict__ in, const float* __restrict__ dww,
    const unsigned char* __restrict__ wt,
    const float* __restrict__ prescale, const float* __restrict__ preshift,
    float* __restrict__ out, float* __restrict__ osum, float* __restrict__ osq)
{
    extern __shared__ char smb[];
    const uint32_t base32 = smem_u32(smb);

    const int tid = threadIdx.x;
    const int wid = tid >> 5;
    const int lane = tid & 31;
    const int n = blockIdx.x >> 4;
    const int sub = blockIdx.x & 15;

    // ---- halo issue for stage s (tile = sub*2 + (s>>2), chunk = s&3) ----
    auto issue_halo = [&](int s) {
        const int tile = sub * 2 + (s >> 2);
        const int th0 = (tile >> 2) * 8;
        const int tw0 = (tile & 3) * 16;
        const int c0 = (s & 3) * 32;
        const uint32_t xsb = base32 + ((s & 1) ? XS1_OFF : XS0_OFF);
        // vector part: 32ch * 10r * 4 = 1280 16B copies (halo cols 1..16, always in-bounds in W)
        #pragma unroll
        for (int u = 0; u < 3; u++) {
            int i = tid + u * 512;
            if (i < 1280) {
                int c = i / 40, rr = i - c * 40;
                int r = rr >> 2, f = rr & 3;
                int gh = th0 - 1 + r;
                bool ok = (unsigned)gh < (unsigned)HH;
                int ghc = ok ? gh : 0;
                const float* src = in + (((size_t)(n * CCH + c0 + c) * HH + ghc) * WW
                                         + tw0 + 4 * f);
                cp_async16(xsb + (uint32_t)(c * XCH + r * XROW + 4 + 4 * f) * 4u,
                           src, ok ? 16u : 0u);
            }
        }
        // scalar part: edge cols h=0 (off 3) and h=17 (off 20): 640 copies
        #pragma unroll
        for (int u = 0; u < 2; u++) {
            int e = tid + u * 512;
            if (e < 640) {
                int c = e / 20, rr = e - c * 20;
                int r = rr >> 1, side = rr & 1;
                int gh = th0 - 1 + r;
                int gw = side ? (tw0 + 16) : (tw0 - 1);
                bool ok = ((unsigned)gh < (unsigned)HH) && ((unsigned)gw < (unsigned)WW);
                const float* src = ok ? in + (((size_t)(n * CCH + c0 + c) * HH + gh) * WW + gw)
                                      : in;
                cp_async4(xsb + (uint32_t)(c * XCH + r * XROW + (side ? 20 : 3)) * 4u,
                          src, ok ? 4u : 0u);
            }
        }
        CP_COMMIT();
    };

    issue_halo(0);

    // ---- W copy into padded smem (vectorized; overlaps stage-0 cp.async) ----
    {
        const float4* whi = (const float4*)wt;     // 2048 f4
        const float4* wlo = whi + 2048;
        #pragma unroll
        for (int u = 0; u < 4; u++) {
            int i = tid + u * 512;                 // < 2048
            int o = i >> 4, seg = i & 15;
            uint32_t off = (uint32_t)o * TSTRIDE + (uint32_t)seg * 16u;
            *(float4*)(smb + WHI_OFF + off) = whi[i];
            *(float4*)(smb + WLO_OFF + off) = wlo[i];
        }
    }

    // GEMM per-warp tiling: 32(o) x 32(px)
    const int o0 = (wid & 3) * 32;
    const int p0 = (wid >> 2) * 32;
    const uint32_t aRow = (uint32_t)(o0 + (lane & 15)) * TSTRIDE + (uint32_t)(lane >> 4) * 16u;
    const uint32_t bRow = (uint32_t)(lane & 15) * TSTRIDE + (uint32_t)(p0 + (lane >> 4) * 8) * 2u;
    const uint32_t aHi0 = base32 + WHI_OFF + aRow;
    const uint32_t aLo0 = base32 + WLO_OFF + aRow;
    const uint32_t bHi0 = base32 + THI_OFF + bRow;
    const uint32_t bLo0 = base32 + TLO_OFF + bRow;

    float d[2][4][4];
    #pragma unroll
    for (int i = 0; i < 2; i++)
        #pragma unroll
        for (int j = 0; j < 4; j++)
            #pragma unroll
            for (int r = 0; r < 4; r++) d[i][j][r] = 0.f;

    for (int s = 0; s < 8; s++) {
        const int tile = sub * 2 + (s >> 2);
        const int th0 = (tile >> 2) * 8;
        const int tw0 = (tile & 3) * 16;
        const int ch = s & 3;
        const int c0 = ch * 32;
        float* xs = (float*)(smb + ((s & 1) ? XS1_OFF : XS0_OFF));

        if (s < 7) issue_halo(s + 1);
        if (s < 7) { CP_WAIT1(); } else { CP_WAIT0(); }
        __syncthreads();   // stage-s halo arrived; all warps past MMA(s-1)

        // ---- warp-local in-place transform: relu(+BN); OOB-zero only needed if PRE_BN ----
        {
            const int cA = 2 * wid;        // this warp's two channels
            float sc0 = 1.f, sh0 = 0.f, sc1 = 1.f, sh1 = 0.f;
            if (PRE_BN) {
                sc0 = prescale[c0 + cA];     sh0 = preshift[c0 + cA];
                sc1 = prescale[c0 + cA + 1]; sh1 = preshift[c0 + cA + 1];
            }
            // 20 rows x (4 float4 + 2 scalar) = 120 slots
            #pragma unroll
            for (int u = 0; u < 4; u++) {
                int slot = lane + u * 32;
                if (slot < 120) {
                    int row2 = slot / 6, v6 = slot - row2 * 6;
                    int chl = row2 >= 10;
                    int row = row2 - 10 * chl;
                    float scv = chl ? sc1 : sc0, shv = chl ? sh1 : sh0;
                    float* rp = xs + (cA + chl) * XCH + row * XROW;
                    int gh = th0 - 1 + row;
                    bool rowok = (unsigned)gh < (unsigned)HH;
                    if (v6 < 4) {
                        float4 v = *(float4*)(rp + 4 + 4 * v6);
                        if (PRE_BN) {
                            v.x = fmaf(v.x, scv, shv); v.y = fmaf(v.y, scv, shv);
                            v.z = fmaf(v.z, scv, shv); v.w = fmaf(v.w, scv, shv);
                        }
                        v.x = fmaxf(v.x, 0.f); v.y = fmaxf(v.y, 0.f);
                        v.z = fmaxf(v.z, 0.f); v.w = fmaxf(v.w, 0.f);
                        if (PRE_BN && !rowok) v = make_float4(0.f, 0.f, 0.f, 0.f);
                        *(float4*)(rp + 4 + 4 * v6) = v;
                    } else {
                        int off = (v6 == 4) ? 3 : 20;
                        bool colok = (v6 == 4) ? (tw0 > 0) : (tw0 < 48);
                        float v = rp[off];
                        if (PRE_BN) v = fmaf(v, scv, shv);
                        v = fmaxf(v, 0.f);
                        if (PRE_BN && !(rowok && colok)) v = 0.f;
                        rp[off] = v;
                    }
                }
            }
            __syncwarp();
        }

        // ---- depthwise 3x3 (vectorized loads), bf16 hi/lo split into T tile ----
        {
            const int cl = tid >> 4;       // local channel 0..31 (warp-consistent: 2wid, 2wid+1)
            const int m = tid & 15;
            const int ph = m >> 1, half = m & 1;
            const float* wp = dww + (c0 + cl) * 9;
            float w0 = wp[0], w1 = wp[1], w2 = wp[2], w3 = wp[3], w4 = wp[4],
                  w5 = wp[5], w6 = wp[6], w7 = wp[7], w8 = wp[8];
            const float* xb = xs + cl * XCH + 8 * half;
            float sacc[8];
            #pragma unroll
            for (int j = 0; j < 8; j++) sacc[j] = 0.f;
            #pragma unroll
            for (int r = 0; r < 3; r++) {
                const float* rp = xb + (ph + r) * XROW;
                float4 A = *(const float4*)(rp);
                float4 B = *(const float4*)(rp + 4);
                float4 C = *(const float4*)(rp + 8);
                float4 D = *(const float4*)(rp + 12);
                float L[16] = {A.x, A.y, A.z, A.w, B.x, B.y, B.z, B.w,
                               C.x, C.y, C.z, C.w, D.x, D.y, D.z, D.w};
                float wr0 = (r == 0) ? w0 : (r == 1) ? w3 : w6;
                float wr1 = (r == 0) ? w1 : (r == 1) ? w4 : w7;
                float wr2 = (r == 0) ? w2 : (r == 1) ? w5 : w8;
                #pragma unroll
                for (int j = 0; j < 8; j++)
                    sacc[j] = fmaf(wr0, L[3 + j],
                              fmaf(wr1, L[4 + j],
                              fmaf(wr2, L[5 + j], sacc[j])));
            }
            uint32_t hiw[4], low[4];
            #pragma unroll
            for (int jp = 0; jp < 4; jp++) {
                float s0 = sacc[2 * jp], s1 = sacc[2 * jp + 1];
                __nv_bfloat16 h0 = __float2bfloat16(s0);
                __nv_bfloat16 h1 = __float2bfloat16(s1);
                __nv_bfloat16 l0 = __float2bfloat16(s0 - __bfloat162float(h0));
                __nv_bfloat16 l1 = __float2bfloat16(s1 - __bfloat162float(h1));
                hiw[jp] = (uint32_t)__bfloat16_as_ushort(h0)
                        | ((uint32_t)__bfloat16_as_ushort(h1) << 16);
                low[jp] = (uint32_t)__bfloat16_as_ushort(l0)
                        | ((uint32_t)__bfloat16_as_ushort(l1) << 16);
            }
            uint32_t toff = (uint32_t)cl * TSTRIDE + (uint32_t)(32 * ph + 16 * half);
            *(uint4*)(smb + THI_OFF + toff) = make_uint4(hiw[0], hiw[1], hiw[2], hiw[3]);
            *(uint4*)(smb + TLO_OFF + toff) = make_uint4(low[0], low[1], low[2], low[3]);
        }
        __syncthreads();   // T(ch) ready

        // ---- MMA for this chunk: 2 k-steps, hi/lo 3-product ----
        #pragma unroll
        for (int kk2 = 0; kk2 < 2; kk2++) {
            const uint32_t ao = (uint32_t)(ch * 2 + kk2) * 32u;
            const uint32_t bo = (uint32_t)kk2 * (16u * TSTRIDE);
            uint32_t ah[2][4], al[2][4], bh[2][4], bl[2][4];
            ldsm_x4(ah[0], aHi0 + ao);
            ldsm_x4(ah[1], aHi0 + ao + 16u * TSTRIDE);
            ldsm_x4(al[0], aLo0 + ao);
            ldsm_x4(al[1], aLo0 + ao + 16u * TSTRIDE);
            ldsmt_x4(bh[0], bHi0 + bo);
            ldsmt_x4(bh[1], bHi0 + bo + 32u);
            ldsmt_x4(bl[0], bLo0 + bo);
            ldsmt_x4(bl[1], bLo0 + bo + 32u);
            #pragma unroll
            for (int i = 0; i < 2; i++) {
                #pragma unroll
                for (int j = 0; j < 4; j++) {
                    const uint32_t* bhf = &bh[j >> 1][(j & 1) * 2];
                    const uint32_t* blf = &bl[j >> 1][(j & 1) * 2];
                    mma16816(d[i][j], ah[i], bhf);
                    mma16816(d[i][j], ah[i], blf);
                    mma16816(d[i][j], al[i], bhf);
                }
            }
        }

        // ---- epilogue after last chunk of the tile ----
        if (ch == 3) {
            const int grp = lane >> 2, tg = lane & 3;
            float* redS = (float*)(smb + RED_OFF);       // 512 floats
            float* redQ = redS + 512;
            #pragma unroll
            for (int i = 0; i < 2; i++) {
                #pragma unroll
                for (int rh = 0; rh < 2; rh++) {
                    int o = o0 + i * 16 + grp + rh * 8;
                    float sv = 0.f, qv = 0.f;
                    #pragma unroll
                    for (int j = 0; j < 4; j++) {
                        int px = p0 + j * 8 + tg * 2;
                        float v0 = d[i][j][rh * 2], v1 = d[i][j][rh * 2 + 1];
                        *(float2*)(out + ((size_t)(n * CCH + o) * HH + th0 + (px >> 4)) * WW
                                         + tw0 + (px & 15)) = make_float2(v0, v1);
                        sv += v0 + v1;
                        qv = fmaf(v0, v0, fmaf(v1, v1, qv));
                    }
                    sv += __shfl_xor_sync(0xffffffffu, sv, 1);
                    sv += __shfl_xor_sync(0xffffffffu, sv, 2);
                    qv += __shfl_xor_sync(0xffffffffu, qv, 1);
                    qv += __shfl_xor_sync(0xffffffffu, qv, 2);
                    if (tg == 0) {
                        redS[o * 4 + (wid >> 2)] = sv;
                        redQ[o * 4 + (wid >> 2)] = qv;
                    }
                }
            }
            // full accumulator reset (only correct place to reset)
            #pragma unroll
            for (int i = 0; i < 2; i++)
                #pragma unroll
                for (int j = 0; j < 4; j++)
                    #pragma unroll
                    for (int r = 0; r < 4; r++) d[i][j][r] = 0.f;
            __syncthreads();
            if (tid < CCH) {
                atomicAdd(&osum[tid], redS[tid * 4] + redS[tid * 4 + 1]
                                    + redS[tid * 4 + 2] + redS[tid * 4 + 3]);
                atomicAdd(&osq[tid], redQ[tid * 4] + redQ[tid * 4 + 1]
                                   + redQ[tid * 4 + 2] + redQ[tid * 4 + 3]);
            }
        }
    }
}

// ---------------- BN helpers ----------------
__global__ void bn_finalize(const float* __restrict__ sum, const float* __restrict__ sq,
                            const float* __restrict__ gamma, const float* __restrict__ beta,
                            float* __restrict__ scale, float* __restrict__ shift) {
    int c = threadIdx.x;
    float inv = 1.0f / NHW_F;
    float m = sum[c] * inv;
    float v = sq[c] * inv - m * m;
    float sc = gamma[c] * rsqrtf(v + EPSV);
    scale[c] = sc;
    shift[c] = beta[c] - m * sc;
}

__global__ void bn_apply(float* __restrict__ y, const float* __restrict__ scale,
                         const float* __restrict__ shift) {
    const int total4 = (NN * CCH * HH * WW) / 4;
    float4* p = (float4*)y;
    for (int i = blockIdx.x * blockDim.x + threadIdx.x; i < total4;
         i += gridDim.x * blockDim.x) {
        int c = (i >> 10) & (CCH - 1);
        float s = scale[c], t = shift[c];
        float4 v = p[i];
        v.x = fmaf(v.x, s, t); v.y = fmaf(v.y, s, t);
        v.z = fmaf(v.z, s, t); v.w = fmaf(v.w, s, t);
        p[i] = v;
    }
}

// ---------------- launch ----------------
extern "C" void kernel_launch(void* const* d_in, const int* in_sizes, int n_in,
                              void* d_out, int out_size) {
    const float* x      = (const float*)d_in[0];
    const float* dw1_w  = (const float*)d_in[1];
    const float* pw1_w  = (const float*)d_in[2];
    const float* gamma1 = (const float*)d_in[3];
    const float* beta1  = (const float*)d_in[4];
    const float* dw2_w  = (const float*)d_in[5];
    const float* pw2_w  = (const float*)d_in[6];
    const float* gamma2 = (const float*)d_in[7];
    const float* beta2  = (const float*)d_in[8];
    float* out = (float*)d_out;

    float *y1, *stats, *sc;
    unsigned char* wt;
    cudaGetSymbolAddress((void**)&y1, g_y1);
    cudaGetSymbolAddress((void**)&stats, g_stats);
    cudaGetSymbolAddress((void**)&sc, g_sc);
    cudaGetSymbolAddress((void**)&wt, g_wt);

    cudaFuncSetAttribute((const void*)conv_mma<false>,
                         cudaFuncAttributeMaxDynamicSharedMemorySize, SMEM_BYTES);
    cudaFuncSetAttribute((const void*)conv_mma<true>,
                         cudaFuncAttributeMaxDynamicSharedMemorySize, SMEM_BYTES);

    prep_w<<<64, 512>>>(pw1_w, pw2_w, wt, stats);

    conv_mma<false><<<512, 512, SMEM_BYTES>>>(x, dw1_w, wt, nullptr, nullptr,
                                              y1, stats, stats + CCH);
    bn_finalize<<<1, CCH>>>(stats, stats + CCH, gamma1, beta1, sc, sc + CCH);

    conv_mma<true><<<512, 512, SMEM_BYTES>>>(y1, dw2_w, wt + 65536, sc, sc + CCH,
                                             out, stats + 2 * CCH, stats + 3 * CCH);
    bn_finalize<<<1, CCH>>>(stats + 2 * CCH, stats + 3 * CCH, gamma2, beta2,
                            sc + 2 * CCH, sc + 3 * CCH);

    bn_apply<<<2048, 256>>>(out, sc + 2 * CCH, sc + 3 * CCH);
}

// round 8
// speedup vs baseline: 2.4927x; 1.1119x over previous
#include <cuda_runtime.h>
#include <cuda_bf16.h>
#include <cstdint>

// ---------------- problem constants ----------------
#define NN 32
#define CCH 128
#define HH 64
#define WW 64
#define NHW_F 131072.0f
#define EPSV 1e-5f

// ---------------- smem layout (byte offsets) ----------------
#define TSTRIDE 272                 // 17x16B segs -> LDSM conflict-free
#define WHI_OFF 0
#define WLO_OFF 34816               // 128*272
#define THI_OFF 69632               // 32*272 = 8704
#define TLO_OFF 78336
#define XS0_OFF 87040
// XS: 32 channels x 10 rows x 24 floats (halo col h at offset h+3, cols 1..16 16B-aligned)
#define XROW 24
#define XCH  240
#define XSBUF_BYTES (32 * XCH * 4)          // 30720
#define XS1_OFF (XS0_OFF + XSBUF_BYTES)     // 117760
#define RED_OFF (XS1_OFF + XSBUF_BYTES)     // 148480
#define SMEM_BYTES (RED_OFF + 4096)         // 152576

// ---------------- device scratch ----------------
__device__ float g_y1[NN * CCH * HH * WW];
__device__ unsigned char g_wt[131072];      // 2 blocks x (hi 32KB + lo 32KB), [o][c]
__device__ float g_stats[4 * CCH];
__device__ float g_sc[4 * CCH];

// ---------------- PTX helpers ----------------
__device__ __forceinline__ uint32_t smem_u32(const void* p) {
    uint32_t a;
    asm("{ .reg .u64 t; cvta.to.shared.u64 t, %1; cvt.u32.u64 %0, t; }" : "=r"(a) : "l"(p));
    return a;
}
__device__ __forceinline__ void ldsm_x4(uint32_t* r, uint32_t a) {
    asm volatile("ldmatrix.sync.aligned.m8n8.x4.shared.b16 {%0,%1,%2,%3}, [%4];"
                 : "=r"(r[0]), "=r"(r[1]), "=r"(r[2]), "=r"(r[3]) : "r"(a));
}
__device__ __forceinline__ void ldsmt_x4(uint32_t* r, uint32_t a) {
    asm volatile("ldmatrix.sync.aligned.m8n8.x4.trans.shared.b16 {%0,%1,%2,%3}, [%4];"
                 : "=r"(r[0]), "=r"(r[1]), "=r"(r[2]), "=r"(r[3]) : "r"(a));
}
__device__ __forceinline__ void mma16816(float* d, const uint32_t* a, const uint32_t* b) {
    asm volatile("mma.sync.aligned.m16n8k16.row.col.f32.bf16.bf16.f32 "
                 "{%0,%1,%2,%3}, {%4,%5,%6,%7}, {%8,%9}, {%0,%1,%2,%3};"
                 : "+f"(d[0]), "+f"(d[1]), "+f"(d[2]), "+f"(d[3])
                 : "r"(a[0]), "r"(a[1]), "r"(a[2]), "r"(a[3]), "r"(b[0]), "r"(b[1]));
}
__device__ __forceinline__ void cp_async4(uint32_t dst, const void* src, uint32_t srcsz) {
    asm volatile("cp.async.ca.shared.global [%0], [%1], 4, %2;"
                 :: "r"(dst), "l"(src), "r"(srcsz) : "memory");
}
__device__ __forceinline__ void cp_async16(uint32_t dst, const void* src, uint32_t srcsz) {
    asm volatile("cp.async.cg.shared.global [%0], [%1], 16, %2;"
                 :: "r"(dst), "l"(src), "r"(srcsz) : "memory");
}
#define CP_COMMIT() asm volatile("cp.async.commit_group;" ::: "memory")
#define CP_WAIT1()  asm volatile("cp.async.wait_group 1;" ::: "memory")
#define CP_WAIT0()  asm volatile("cp.async.wait_group 0;" ::: "memory")

// ---------------- prep: split pw weights to bf16 hi/lo; zero stats ----------------
__global__ void prep_w(const float* __restrict__ pw1, const float* __restrict__ pw2,
                       unsigned char* __restrict__ wt, float* __restrict__ stats) {
    int idx = blockIdx.x * blockDim.x + threadIdx.x;
    if (idx < 4 * CCH) stats[idx] = 0.f;
    if (idx >= 32768) return;
    int blk = idx >> 14;
    int w = idx & 16383;
    float v = (blk ? pw2 : pw1)[w];
    __nv_bfloat16 h = __float2bfloat16(v);
    __nv_bfloat16 l = __float2bfloat16(v - __bfloat162float(h));
    unsigned char* base = wt + (uint32_t)blk * 65536u;
    *(__nv_bfloat16*)(base + (uint32_t)w * 2u) = h;
    *(__nv_bfloat16*)(base + 32768u + (uint32_t)w * 2u) = l;
}

// ---------------- fused relu(+BN) -> dw3x3 -> HMMA pointwise + stats ----------------
// 512 CTAs x 512 threads; each CTA: 2 tiles x 4 chunk-stages, cp.async pipelined.
// Transform (relu + optional BN) is fused into the depthwise register loads.
template <bool PRE_BN>
__global__ __launch_bounds__(512, 1) void conv_mma(
    const float* __restrict__ in, const float* __restrict__ dww,
    const unsigned char* __restrict__ wt,
    const float* __restrict__ prescale, const float* __restrict__ preshift,
    float* __restrict__ out, float* __restrict__ osum, float* __restrict__ osq)
{
    extern __shared__ char smb[];
    const uint32_t base32 = smem_u32(smb);

    const int tid = threadIdx.x;
    const int wid = tid >> 5;
    const int lane = tid & 31;
    const int n = blockIdx.x >> 4;
    const int sub = blockIdx.x & 15;

    // ---- halo issue for stage s (tile = sub*2 + (s>>2), chunk = s&3) ----
    auto issue_halo = [&](int s) {
        const int tile = sub * 2 + (s >> 2);
        const int th0 = (tile >> 2) * 8;
        const int tw0 = (tile & 3) * 16;
        const int c0 = (s & 3) * 32;
        const uint32_t xsb = base32 + ((s & 1) ? XS1_OFF : XS0_OFF);
        // vector part: 32ch * 10r * 4 = 1280 16B copies
        #pragma unroll
        for (int u = 0; u < 3; u++) {
            int i = tid + u * 512;
            if (i < 1280) {
                int c = i / 40, rr = i - c * 40;
                int r = rr >> 2, f = rr & 3;
                int gh = th0 - 1 + r;
                bool ok = (unsigned)gh < (unsigned)HH;
                int ghc = ok ? gh : 0;
                const float* src = in + (((size_t)(n * CCH + c0 + c) * HH + ghc) * WW
                                         + tw0 + 4 * f);
                cp_async16(xsb + (uint32_t)(c * XCH + r * XROW + 4 + 4 * f) * 4u,
                           src, ok ? 16u : 0u);
            }
        }
        // scalar part: edge cols h=0 (off 3) and h=17 (off 20): 640 copies
        #pragma unroll
        for (int u = 0; u < 2; u++) {
            int e = tid + u * 512;
            if (e < 640) {
                int c = e / 20, rr = e - c * 20;
                int r = rr >> 1, side = rr & 1;
                int gh = th0 - 1 + r;
                int gw = side ? (tw0 + 16) : (tw0 - 1);
                bool ok = ((unsigned)gh < (unsigned)HH) && ((unsigned)gw < (unsigned)WW);
                const float* src = ok ? in + (((size_t)(n * CCH + c0 + c) * HH + gh) * WW + gw)
                                      : in;
                cp_async4(xsb + (uint32_t)(c * XCH + r * XROW + (side ? 20 : 3)) * 4u,
                          src, ok ? 4u : 0u);
            }
        }
        CP_COMMIT();
    };

    issue_halo(0);

    // ---- W copy into padded smem (vectorized; overlaps stage-0 cp.async) ----
    {
        const float4* whi = (const float4*)wt;     // 2048 f4
        const float4* wlo = whi + 2048;
        #pragma unroll
        for (int u = 0; u < 4; u++) {
            int i = tid + u * 512;                 // < 2048
            int o = i >> 4, seg = i & 15;
            uint32_t off = (uint32_t)o * TSTRIDE + (uint32_t)seg * 16u;
            *(float4*)(smb + WHI_OFF + off) = whi[i];
            *(float4*)(smb + WLO_OFF + off) = wlo[i];
        }
    }

    // ---- preload per-chunk BN scale/shift for this thread's dw channel ----
    const int cl = tid >> 4;           // local channel 0..31
    const int m = tid & 15;
    const int ph = m >> 1, half = m & 1;
    float scs[4], shs[4];
    if (PRE_BN) {
        #pragma unroll
        for (int ch = 0; ch < 4; ch++) {
            scs[ch] = prescale[ch * 32 + cl];
            shs[ch] = preshift[ch * 32 + cl];
        }
    }
    // depthwise weights for all 4 chunks' channel: 9 floats each -> load per chunk (L1-hit)

    // GEMM per-warp tiling: 32(o) x 32(px)
    const int o0 = (wid & 3) * 32;
    const int p0 = (wid >> 2) * 32;
    const uint32_t aRow = (uint32_t)(o0 + (lane & 15)) * TSTRIDE + (uint32_t)(lane >> 4) * 16u;
    const uint32_t bRow = (uint32_t)(lane & 15) * TSTRIDE + (uint32_t)(p0 + (lane >> 4) * 8) * 2u;
    const uint32_t aHi0 = base32 + WHI_OFF + aRow;
    const uint32_t aLo0 = base32 + WLO_OFF + aRow;
    const uint32_t bHi0 = base32 + THI_OFF + bRow;
    const uint32_t bLo0 = base32 + TLO_OFF + bRow;

    float d[2][4][4];
    #pragma unroll
    for (int i = 0; i < 2; i++)
        #pragma unroll
        for (int j = 0; j < 4; j++)
            #pragma unroll
            for (int r = 0; r < 4; r++) d[i][j][r] = 0.f;

    for (int s = 0; s < 8; s++) {
        const int tile = sub * 2 + (s >> 2);
        const int th0 = (tile >> 2) * 8;
        const int tw0 = (tile & 3) * 16;
        const int ch = s & 3;
        const int c0 = ch * 32;
        float* xs = (float*)(smb + ((s & 1) ? XS1_OFF : XS0_OFF));

        if (s < 7) issue_halo(s + 1);
        if (s < 7) { CP_WAIT1(); } else { CP_WAIT0(); }
        __syncthreads();   // stage-s halo arrived; all warps past MMA(s-1)

        // ---- depthwise 3x3 with fused relu(+BN) on register loads ----
        {
            const float* wp = dww + (c0 + cl) * 9;
            float w0 = wp[0], w1 = wp[1], w2 = wp[2], w3 = wp[3], w4 = wp[4],
                  w5 = wp[5], w6 = wp[6], w7 = wp[7], w8 = wp[8];
            const float scv = PRE_BN ? scs[ch] : 1.f;
            const float shv = PRE_BN ? shs[ch] : 0.f;
            const float* xb = xs + cl * XCH + 8 * half;
            float sacc[8];
            #pragma unroll
            for (int j = 0; j < 8; j++) sacc[j] = 0.f;
            #pragma unroll
            for (int r = 0; r < 3; r++) {
                const int gh = th0 - 1 + ph + r;
                const bool rowok = (unsigned)gh < (unsigned)HH;
                if (PRE_BN && !rowok) continue;     // whole row contributes zero
                const float* rp = xb + (ph + r) * XROW;
                float4 A = *(const float4*)(rp);
                float4 B = *(const float4*)(rp + 4);
                float4 C = *(const float4*)(rp + 8);
                float4 D = *(const float4*)(rp + 12);
                float L[16] = {A.x, A.y, A.z, A.w, B.x, B.y, B.z, B.w,
                               C.x, C.y, C.z, C.w, D.x, D.y, D.z, D.w};
                if (PRE_BN) {
                    #pragma unroll
                    for (int j = 0; j < 16; j++)
                        L[j] = fmaxf(fmaf(L[j], scv, shv), 0.f);
                    if (half == 0 && tw0 == 0) L[3] = 0.f;      // left border col
                    if (half == 1 && tw0 == 48) L[12] = 0.f;    // right border col
                } else {
                    #pragma unroll
                    for (int j = 0; j < 16; j++)
                        L[j] = fmaxf(L[j], 0.f);                // zfill OOB stays 0
                }
                float wr0 = (r == 0) ? w0 : (r == 1) ? w3 : w6;
                float wr1 = (r == 0) ? w1 : (r == 1) ? w4 : w7;
                float wr2 = (r == 0) ? w2 : (r == 1) ? w5 : w8;
                #pragma unroll
                for (int j = 0; j < 8; j++)
                    sacc[j] = fmaf(wr0, L[3 + j],
                              fmaf(wr1, L[4 + j],
                              fmaf(wr2, L[5 + j], sacc[j])));
            }
            uint32_t hiw[4], low[4];
            #pragma unroll
            for (int jp = 0; jp < 4; jp++) {
                float s0 = sacc[2 * jp], s1 = sacc[2 * jp + 1];
                __nv_bfloat16 h0 = __float2bfloat16(s0);
                __nv_bfloat16 h1 = __float2bfloat16(s1);
                __nv_bfloat16 l0 = __float2bfloat16(s0 - __bfloat162float(h0));
                __nv_bfloat16 l1 = __float2bfloat16(s1 - __bfloat162float(h1));
                hiw[jp] = (uint32_t)__bfloat16_as_ushort(h0)
                        | ((uint32_t)__bfloat16_as_ushort(h1) << 16);
                low[jp] = (uint32_t)__bfloat16_as_ushort(l0)
                        | ((uint32_t)__bfloat16_as_ushort(l1) << 16);
            }
            uint32_t toff = (uint32_t)cl * TSTRIDE + (uint32_t)(32 * ph + 16 * half);
            *(uint4*)(smb + THI_OFF + toff) = make_uint4(hiw[0], hiw[1], hiw[2], hiw[3]);
            *(uint4*)(smb + TLO_OFF + toff) = make_uint4(low[0], low[1], low[2], low[3]);
        }
        __syncthreads();   // T(ch) ready

        // ---- MMA for this chunk: 2 k-steps, hi/lo 3-product ----
        #pragma unroll
        for (int kk2 = 0; kk2 < 2; kk2++) {
            const uint32_t ao = (uint32_t)(ch * 2 + kk2) * 32u;
            const uint32_t bo = (uint32_t)kk2 * (16u * TSTRIDE);
            uint32_t ah[2][4], al[2][4], bh[2][4], bl[2][4];
            ldsm_x4(ah[0], aHi0 + ao);
            ldsm_x4(ah[1], aHi0 + ao + 16u * TSTRIDE);
            ldsm_x4(al[0], aLo0 + ao);
            ldsm_x4(al[1], aLo0 + ao + 16u * TSTRIDE);
            ldsmt_x4(bh[0], bHi0 + bo);
            ldsmt_x4(bh[1], bHi0 + bo + 32u);
            ldsmt_x4(bl[0], bLo0 + bo);
            ldsmt_x4(bl[1], bLo0 + bo + 32u);
            #pragma unroll
            for (int i = 0; i < 2; i++) {
                #pragma unroll
                for (int j = 0; j < 4; j++) {
                    const uint32_t* bhf = &bh[j >> 1][(j & 1) * 2];
                    const uint32_t* blf = &bl[j >> 1][(j & 1) * 2];
                    mma16816(d[i][j], ah[i], bhf);
                    mma16816(d[i][j], ah[i], blf);
                    mma16816(d[i][j], al[i], bhf);
                }
            }
        }

        // ---- epilogue after last chunk of the tile ----
        if (ch == 3) {
            const int grp = lane >> 2, tg = lane & 3;
            float* redS = (float*)(smb + RED_OFF);       // 512 floats
            float* redQ = redS + 512;
            #pragma unroll
            for (int i = 0; i < 2; i++) {
                #pragma unroll
                for (int rh = 0; rh < 2; rh++) {
                    int o = o0 + i * 16 + grp + rh * 8;
                    float sv = 0.f, qv = 0.f;
                    #pragma unroll
                    for (int j = 0; j < 4; j++) {
                        int px = p0 + j * 8 + tg * 2;
                        float v0 = d[i][j][rh * 2], v1 = d[i][j][rh * 2 + 1];
                        *(float2*)(out + ((size_t)(n * CCH + o) * HH + th0 + (px >> 4)) * WW
                                         + tw0 + (px & 15)) = make_float2(v0, v1);
                        sv += v0 + v1;
                        qv = fmaf(v0, v0, fmaf(v1, v1, qv));
                    }
                    sv += __shfl_xor_sync(0xffffffffu, sv, 1);
                    sv += __shfl_xor_sync(0xffffffffu, sv, 2);
                    qv += __shfl_xor_sync(0xffffffffu, qv, 1);
                    qv += __shfl_xor_sync(0xffffffffu, qv, 2);
                    if (tg == 0) {
                        redS[o * 4 + (wid >> 2)] = sv;
                        redQ[o * 4 + (wid >> 2)] = qv;
                    }
                }
            }
            // full accumulator reset
            #pragma unroll
            for (int i = 0; i < 2; i++)
                #pragma unroll
                for (int j = 0; j < 4; j++)
                    #pragma unroll
                    for (int r = 0; r < 4; r++) d[i][j][r] = 0.f;
            __syncthreads();
            if (tid < CCH) {
                atomicAdd(&osum[tid], redS[tid * 4] + redS[tid * 4 + 1]
                                    + redS[tid * 4 + 2] + redS[tid * 4 + 3]);
                atomicAdd(&osq[tid], redQ[tid * 4] + redQ[tid * 4 + 1]
                                   + redQ[tid * 4 + 2] + redQ[tid * 4 + 3]);
            }
        }
    }
}

// ---------------- BN helpers ----------------
__global__ void bn_finalize(const float* __restrict__ sum, const float* __restrict__ sq,
                            const float* __restrict__ gamma, const float* __restrict__ beta,
                            float* __restrict__ scale, float* __restrict__ shift) {
    int c = threadIdx.x;
    float inv = 1.0f / NHW_F;
    float m = sum[c] * inv;
    float v = sq[c] * inv - m * m;
    float sc = gamma[c] * rsqrtf(v + EPSV);
    scale[c] = sc;
    shift[c] = beta[c] - m * sc;
}

__global__ void bn_apply(float* __restrict__ y, const float* __restrict__ scale,
                         const float* __restrict__ shift) {
    const int total4 = (NN * CCH * HH * WW) / 4;
    float4* p = (float4*)y;
    for (int i = blockIdx.x * blockDim.x + threadIdx.x; i < total4;
         i += gridDim.x * blockDim.x) {
        int c = (i >> 10) & (CCH - 1);
        float s = scale[c], t = shift[c];
        float4 v = p[i];
        v.x = fmaf(v.x, s, t); v.y = fmaf(v.y, s, t);
        v.z = fmaf(v.z, s, t); v.w = fmaf(v.w, s, t);
        p[i] = v;
    }
}

// ---------------- launch ----------------
extern "C" void kernel_launch(void* const* d_in, const int* in_sizes, int n_in,
                              void* d_out, int out_size) {
    const float* x      = (const float*)d_in[0];
    const float* dw1_w  = (const float*)d_in[1];
    const float* pw1_w  = (const float*)d_in[2];
    const float* gamma1 = (const float*)d_in[3];
    const float* beta1  = (const float*)d_in[4];
    const float* dw2_w  = (const float*)d_in[5];
    const float* pw2_w  = (const float*)d_in[6];
    const float* gamma2 = (const float*)d_in[7];
    const float* beta2  = (const float*)d_in[8];
    float* out = (float*)d_out;

    float *y1, *stats, *sc;
    unsigned char* wt;
    cudaGetSymbolAddress((void**)&y1, g_y1);
    cudaGetSymbolAddress((void**)&stats, g_stats);
    cudaGetSymbolAddress((void**)&sc, g_sc);
    cudaGetSymbolAddress((void**)&wt, g_wt);

    cudaFuncSetAttribute((const void*)conv_mma<false>,
                         cudaFuncAttributeMaxDynamicSharedMemorySize, SMEM_BYTES);
    cudaFuncSetAttribute((const void*)conv_mma<true>,
                         cudaFuncAttributeMaxDynamicSharedMemorySize, SMEM_BYTES);

    prep_w<<<64, 512>>>(pw1_w, pw2_w, wt, stats);

    conv_mma<false><<<512, 512, SMEM_BYTES>>>(x, dw1_w, wt, nullptr, nullptr,
                                              y1, stats, stats + CCH);
    bn_finalize<<<1, CCH>>>(stats, stats + CCH, gamma1, beta1, sc, sc + CCH);

    conv_mma<true><<<512, 512, SMEM_BYTES>>>(y1, dw2_w, wt + 65536, sc, sc + CCH,
                                             out, stats + 2 * CCH, stats + 3 * CCH);
    bn_finalize<<<1, CCH>>>(stats + 2 * CCH, stats + 3 * CCH, gamma2, beta2,
                            sc + 2 * CCH, sc + 3 * CCH);

    bn_apply<<<2048, 256>>>(out, sc + 2 * CCH, sc + 3 * CCH);
}

// round 9
// speedup vs baseline: 2.7063x; 1.0857x over previous
#include <cuda_runtime.h>
#include <cuda_fp16.h>
#include <cstdint>

// ---------------- problem constants ----------------
#define NN 32
#define CCH 128
#define HH 64
#define WW 64
#define NHW_F 131072.0f
#define EPSV 1e-5f

// ---------------- smem layout (byte offsets) ----------------
#define TSTRIDE 272                 // 17x16B segs -> LDSM conflict-free
#define WHI_OFF 0
#define WLO_OFF 34816               // 128*272
#define THI_OFF 69632               // 32*272 = 8704
#define XS0_OFF 78336
// XS: 32 channels x 10 rows x 24 floats (halo col h at offset h+3, cols 1..16 16B-aligned)
#define XROW 24
#define XCH  240
#define XSBUF_BYTES (32 * XCH * 4)          // 30720
#define XS1_OFF (XS0_OFF + XSBUF_BYTES)     // 109056
#define RED_OFF (XS1_OFF + XSBUF_BYTES)     // 139776
#define SMEM_BYTES (RED_OFF + 4096)         // 143872

// ---------------- device scratch ----------------
__device__ float g_y1[NN * CCH * HH * WW];
__device__ unsigned char g_wt[131072];      // 2 blocks x (hi 32KB + lo 32KB), [o][c] fp16
__device__ float g_stats[4 * CCH];
__device__ float g_sc[4 * CCH];

// ---------------- PTX helpers ----------------
__device__ __forceinline__ uint32_t smem_u32(const void* p) {
    uint32_t a;
    asm("{ .reg .u64 t; cvta.to.shared.u64 t, %1; cvt.u32.u64 %0, t; }" : "=r"(a) : "l"(p));
    return a;
}
__device__ __forceinline__ void ldsm_x4(uint32_t* r, uint32_t a) {
    asm volatile("ldmatrix.sync.aligned.m8n8.x4.shared.b16 {%0,%1,%2,%3}, [%4];"
                 : "=r"(r[0]), "=r"(r[1]), "=r"(r[2]), "=r"(r[3]) : "r"(a));
}
__device__ __forceinline__ void ldsmt_x4(uint32_t* r, uint32_t a) {
    asm volatile("ldmatrix.sync.aligned.m8n8.x4.trans.shared.b16 {%0,%1,%2,%3}, [%4];"
                 : "=r"(r[0]), "=r"(r[1]), "=r"(r[2]), "=r"(r[3]) : "r"(a));
}
__device__ __forceinline__ void mma16816h(float* d, const uint32_t* a, const uint32_t* b) {
    asm volatile("mma.sync.aligned.m16n8k16.row.col.f32.f16.f16.f32 "
                 "{%0,%1,%2,%3}, {%4,%5,%6,%7}, {%8,%9}, {%0,%1,%2,%3};"
                 : "+f"(d[0]), "+f"(d[1]), "+f"(d[2]), "+f"(d[3])
                 : "r"(a[0]), "r"(a[1]), "r"(a[2]), "r"(a[3]), "r"(b[0]), "r"(b[1]));
}
__device__ __forceinline__ void cp_async4(uint32_t dst, const void* src, uint32_t srcsz) {
    asm volatile("cp.async.ca.shared.global [%0], [%1], 4, %2;"
                 :: "r"(dst), "l"(src), "r"(srcsz) : "memory");
}
__device__ __forceinline__ void cp_async16(uint32_t dst, const void* src, uint32_t srcsz) {
    asm volatile("cp.async.cg.shared.global [%0], [%1], 16, %2;"
                 :: "r"(dst), "l"(src), "r"(srcsz) : "memory");
}
#define CP_COMMIT() asm volatile("cp.async.commit_group;" ::: "memory")
#define CP_WAIT1()  asm volatile("cp.async.wait_group 1;" ::: "memory")
#define CP_WAIT0()  asm volatile("cp.async.wait_group 0;" ::: "memory")

// ---------------- prep: split pw weights to fp16 hi/lo; zero stats ----------------
__global__ void prep_w(const float* __restrict__ pw1, const float* __restrict__ pw2,
                       unsigned char* __restrict__ wt, float* __restrict__ stats) {
    int idx = blockIdx.x * blockDim.x + threadIdx.x;
    if (idx < 4 * CCH) stats[idx] = 0.f;
    if (idx >= 32768) return;
    int blk = idx >> 14;
    int w = idx & 16383;
    float v = (blk ? pw2 : pw1)[w];
    __half h = __float2half_rn(v);
    __half l = __float2half_rn(v - __half2float(h));
    unsigned char* base = wt + (uint32_t)blk * 65536u;
    *(__half*)(base + (uint32_t)w * 2u) = h;
    *(__half*)(base + 32768u + (uint32_t)w * 2u) = l;
}

// ---------------- fused relu(+BN) -> dw3x3 -> HMMA(fp16) pointwise + stats ----------------
// 512 CTAs x 512 threads; each CTA: 2 tiles x 4 chunk-stages, cp.async pipelined.
// W = Whi + Wlo (fp16 2-product); activations single fp16.
template <bool PRE_BN>
__global__ __launch_bounds__(512, 1) void conv_mma(
    const float* __restrict__ in, const float* __restrict__ dww,
    const unsigned char* __restrict__ wt,
    const float* __restrict__ prescale, const float* __restrict__ preshift,
    float* __restrict__ out, float* __restrict__ osum, float* __restrict__ osq)
{
    extern __shared__ char smb[];
    const uint32_t base32 = smem_u32(smb);

    const int tid = threadIdx.x;
    const int wid = tid >> 5;
    const int lane = tid & 31;
    const int n = blockIdx.x >> 4;
    const int sub = blockIdx.x & 15;

    // ---- halo issue for stage s (tile = sub*2 + (s>>2), chunk = s&3) ----
    auto issue_halo = [&](int s) {
        const int tile = sub * 2 + (s >> 2);
        const int th0 = (tile >> 2) * 8;
        const int tw0 = (tile & 3) * 16;
        const int c0 = (s & 3) * 32;
        const uint32_t xsb = base32 + ((s & 1) ? XS1_OFF : XS0_OFF);
        // vector part: 32ch * 10r * 4 = 1280 16B copies
        #pragma unroll
        for (int u = 0; u < 3; u++) {
            int i = tid + u * 512;
            if (i < 1280) {
                int c = i / 40, rr = i - c * 40;
                int r = rr >> 2, f = rr & 3;
                int gh = th0 - 1 + r;
                bool ok = (unsigned)gh < (unsigned)HH;
                int ghc = ok ? gh : 0;
                const float* src = in + (((size_t)(n * CCH + c0 + c) * HH + ghc) * WW
                                         + tw0 + 4 * f);
                cp_async16(xsb + (uint32_t)(c * XCH + r * XROW + 4 + 4 * f) * 4u,
                           src, ok ? 16u : 0u);
            }
        }
        // scalar part: edge cols h=0 (off 3) and h=17 (off 20): 640 copies
        #pragma unroll
        for (int u = 0; u < 2; u++) {
            int e = tid + u * 512;
            if (e < 640) {
                int c = e / 20, rr = e - c * 20;
                int r = rr >> 1, side = rr & 1;
                int gh = th0 - 1 + r;
                int gw = side ? (tw0 + 16) : (tw0 - 1);
                bool ok = ((unsigned)gh < (unsigned)HH) && ((unsigned)gw < (unsigned)WW);
                const float* src = ok ? in + (((size_t)(n * CCH + c0 + c) * HH + gh) * WW + gw)
                                      : in;
                cp_async4(xsb + (uint32_t)(c * XCH + r * XROW + (side ? 20 : 3)) * 4u,
                          src, ok ? 4u : 0u);
            }
        }
        CP_COMMIT();
    };

    issue_halo(0);

    // ---- W copy into padded smem (vectorized; overlaps stage-0 cp.async) ----
    {
        const float4* whi = (const float4*)wt;     // 2048 f4
        const float4* wlo = whi + 2048;
        #pragma unroll
        for (int u = 0; u < 4; u++) {
            int i = tid + u * 512;                 // < 2048
            int o = i >> 4, seg = i & 15;
            uint32_t off = (uint32_t)o * TSTRIDE + (uint32_t)seg * 16u;
            *(float4*)(smb + WHI_OFF + off) = whi[i];
            *(float4*)(smb + WLO_OFF + off) = wlo[i];
        }
    }

    // ---- preload per-chunk BN scale/shift for this thread's dw channel ----
    const int cl = tid >> 4;           // local channel 0..31
    const int m = tid & 15;
    const int ph = m >> 1, half = m & 1;
    float scs[4], shs[4];
    if (PRE_BN) {
        #pragma unroll
        for (int ch = 0; ch < 4; ch++) {
            scs[ch] = prescale[ch * 32 + cl];
            shs[ch] = preshift[ch * 32 + cl];
        }
    }

    // GEMM per-warp tiling: 32(o) x 32(px)
    const int o0 = (wid & 3) * 32;
    const int p0 = (wid >> 2) * 32;
    const uint32_t aRow = (uint32_t)(o0 + (lane & 15)) * TSTRIDE + (uint32_t)(lane >> 4) * 16u;
    const uint32_t bRow = (uint32_t)(lane & 15) * TSTRIDE + (uint32_t)(p0 + (lane >> 4) * 8) * 2u;
    const uint32_t aHi0 = base32 + WHI_OFF + aRow;
    const uint32_t aLo0 = base32 + WLO_OFF + aRow;
    const uint32_t bHi0 = base32 + THI_OFF + bRow;

    float d[2][4][4];
    #pragma unroll
    for (int i = 0; i < 2; i++)
        #pragma unroll
        for (int j = 0; j < 4; j++)
            #pragma unroll
            for (int r = 0; r < 4; r++) d[i][j][r] = 0.f;

    for (int s = 0; s < 8; s++) {
        const int tile = sub * 2 + (s >> 2);
        const int th0 = (tile >> 2) * 8;
        const int tw0 = (tile & 3) * 16;
        const int ch = s & 3;
        const int c0 = ch * 32;
        float* xs = (float*)(smb + ((s & 1) ? XS1_OFF : XS0_OFF));

        if (s < 7) issue_halo(s + 1);
        if (s < 7) { CP_WAIT1(); } else { CP_WAIT0(); }
        __syncthreads();   // stage-s halo arrived; all warps past MMA(s-1)

        // ---- depthwise 3x3 with fused relu(+BN) on register loads ----
        {
            const float* wp = dww + (c0 + cl) * 9;
            float w0 = wp[0], w1 = wp[1], w2 = wp[2], w3 = wp[3], w4 = wp[4],
                  w5 = wp[5], w6 = wp[6], w7 = wp[7], w8 = wp[8];
            const float scv = PRE_BN ? scs[ch] : 1.f;
            const float shv = PRE_BN ? shs[ch] : 0.f;
            const float* xb = xs + cl * XCH + 8 * half;
            float sacc[8];
            #pragma unroll
            for (int j = 0; j < 8; j++) sacc[j] = 0.f;
            #pragma unroll
            for (int r = 0; r < 3; r++) {
                const int gh = th0 - 1 + ph + r;
                const bool rowok = (unsigned)gh < (unsigned)HH;
                if (PRE_BN && !rowok) continue;     // whole row contributes zero
                const float* rp = xb + (ph + r) * XROW;
                float4 A = *(const float4*)(rp);
                float4 B = *(const float4*)(rp + 4);
                float4 C = *(const float4*)(rp + 8);
                float4 D = *(const float4*)(rp + 12);
                float L[16] = {A.x, A.y, A.z, A.w, B.x, B.y, B.z, B.w,
                               C.x, C.y, C.z, C.w, D.x, D.y, D.z, D.w};
                if (PRE_BN) {
                    #pragma unroll
                    for (int j = 0; j < 16; j++)
                        L[j] = fmaxf(fmaf(L[j], scv, shv), 0.f);
                    if (half == 0 && tw0 == 0) L[3] = 0.f;      // left border col
                    if (half == 1 && tw0 == 48) L[12] = 0.f;    // right border col
                } else {
                    #pragma unroll
                    for (int j = 0; j < 16; j++)
                        L[j] = fmaxf(L[j], 0.f);                // zfill OOB stays 0
                }
                float wr0 = (r == 0) ? w0 : (r == 1) ? w3 : w6;
                float wr1 = (r == 0) ? w1 : (r == 1) ? w4 : w7;
                float wr2 = (r == 0) ? w2 : (r == 1) ? w5 : w8;
                #pragma unroll
                for (int j = 0; j < 8; j++)
                    sacc[j] = fmaf(wr0, L[3 + j],
                              fmaf(wr1, L[4 + j],
                              fmaf(wr2, L[5 + j], sacc[j])));
            }
            uint32_t hiw[4];
            #pragma unroll
            for (int jp = 0; jp < 4; jp++) {
                __half h0 = __float2half_rn(sacc[2 * jp]);
                __half h1 = __float2half_rn(sacc[2 * jp + 1]);
                hiw[jp] = (uint32_t)__half_as_ushort(h0)
                        | ((uint32_t)__half_as_ushort(h1) << 16);
            }
            uint32_t toff = (uint32_t)cl * TSTRIDE + (uint32_t)(32 * ph + 16 * half);
            *(uint4*)(smb + THI_OFF + toff) = make_uint4(hiw[0], hiw[1], hiw[2], hiw[3]);
        }
        __syncthreads();   // T(ch) ready

        // ---- MMA for this chunk: 2 k-steps, (Whi + Wlo) x T ----
        #pragma unroll
        for (int kk2 = 0; kk2 < 2; kk2++) {
            const uint32_t ao = (uint32_t)(ch * 2 + kk2) * 32u;
            const uint32_t bo = (uint32_t)kk2 * (16u * TSTRIDE);
            uint32_t ah[2][4], al[2][4], bh[2][4];
            ldsm_x4(ah[0], aHi0 + ao);
            ldsm_x4(ah[1], aHi0 + ao + 16u * TSTRIDE);
            ldsm_x4(al[0], aLo0 + ao);
            ldsm_x4(al[1], aLo0 + ao + 16u * TSTRIDE);
            ldsmt_x4(bh[0], bHi0 + bo);
            ldsmt_x4(bh[1], bHi0 + bo + 32u);
            #pragma unroll
            for (int i = 0; i < 2; i++) {
                #pragma unroll
                for (int j = 0; j < 4; j++) {
                    const uint32_t* bhf = &bh[j >> 1][(j & 1) * 2];
                    mma16816h(d[i][j], ah[i], bhf);
                    mma16816h(d[i][j], al[i], bhf);
                }
            }
        }

        // ---- epilogue after last chunk of the tile ----
        if (ch == 3) {
            const int grp = lane >> 2, tg = lane & 3;
            float* redS = (float*)(smb + RED_OFF);       // 512 floats
            float* redQ = redS + 512;
            #pragma unroll
            for (int i = 0; i < 2; i++) {
                #pragma unroll
                for (int rh = 0; rh < 2; rh++) {
                    int o = o0 + i * 16 + grp + rh * 8;
                    float sv = 0.f, qv = 0.f;
                    #pragma unroll
                    for (int j = 0; j < 4; j++) {
                        int px = p0 + j * 8 + tg * 2;
                        float v0 = d[i][j][rh * 2], v1 = d[i][j][rh * 2 + 1];
                        *(float2*)(out + ((size_t)(n * CCH + o) * HH + th0 + (px >> 4)) * WW
                                         + tw0 + (px & 15)) = make_float2(v0, v1);
                        sv += v0 + v1;
                        qv = fmaf(v0, v0, fmaf(v1, v1, qv));
                    }
                    sv += __shfl_xor_sync(0xffffffffu, sv, 1);
                    sv += __shfl_xor_sync(0xffffffffu, sv, 2);
                    qv += __shfl_xor_sync(0xffffffffu, qv, 1);
                    qv += __shfl_xor_sync(0xffffffffu, qv, 2);
                    if (tg == 0) {
                        redS[o * 4 + (wid >> 2)] = sv;
                        redQ[o * 4 + (wid >> 2)] = qv;
                    }
                }
            }
            // full accumulator reset
            #pragma unroll
            for (int i = 0; i < 2; i++)
                #pragma unroll
                for (int j = 0; j < 4; j++)
                    #pragma unroll
                    for (int r = 0; r < 4; r++) d[i][j][r] = 0.f;
            __syncthreads();
            if (tid < CCH) {
                atomicAdd(&osum[tid], redS[tid * 4] + redS[tid * 4 + 1]
                                    + redS[tid * 4 + 2] + redS[tid * 4 + 3]);
                atomicAdd(&osq[tid], redQ[tid * 4] + redQ[tid * 4 + 1]
                                   + redQ[tid * 4 + 2] + redQ[tid * 4 + 3]);
            }
        }
    }
}

// ---------------- BN helpers ----------------
__global__ void bn_finalize(const float* __restrict__ sum, const float* __restrict__ sq,
                            const float* __restrict__ gamma, const float* __restrict__ beta,
                            float* __restrict__ scale, float* __restrict__ shift) {
    int c = threadIdx.x;
    float inv = 1.0f / NHW_F;
    float m = sum[c] * inv;
    float v = sq[c] * inv - m * m;
    float sc = gamma[c] * rsqrtf(v + EPSV);
    scale[c] = sc;
    shift[c] = beta[c] - m * sc;
}

__global__ void bn_apply(float* __restrict__ y, const float* __restrict__ scale,
                         const float* __restrict__ shift) {
    const int total4 = (NN * CCH * HH * WW) / 4;
    float4* p = (float4*)y;
    for (int i = blockIdx.x * blockDim.x + threadIdx.x; i < total4;
         i += gridDim.x * blockDim.x) {
        int c = (i >> 10) & (CCH - 1);
        float s = scale[c], t = shift[c];
        float4 v = p[i];
        v.x = fmaf(v.x, s, t); v.y = fmaf(v.y, s, t);
        v.z = fmaf(v.z, s, t); v.w = fmaf(v.w, s, t);
        p[i] = v;
    }
}

// ---------------- launch ----------------
extern "C" void kernel_launch(void* const* d_in, const int* in_sizes, int n_in,
                              void* d_out, int out_size) {
    const float* x      = (const float*)d_in[0];
    const float* dw1_w  = (const float*)d_in[1];
    const float* pw1_w  = (const float*)d_in[2];
    const float* gamma1 = (const float*)d_in[3];
    const float* beta1  = (const float*)d_in[4];
    const float* dw2_w  = (const float*)d_in[5];
    const float* pw2_w  = (const float*)d_in[6];
    const float* gamma2 = (const float*)d_in[7];
    const float* beta2  = (const float*)d_in[8];
    float* out = (float*)d_out;

    float *y1, *stats, *sc;
    unsigned char* wt;
    cudaGetSymbolAddress((void**)&y1, g_y1);
    cudaGetSymbolAddress((void**)&stats, g_stats);
    cudaGetSymbolAddress((void**)&sc, g_sc);
    cudaGetSymbolAddress((void**)&wt, g_wt);

    cudaFuncSetAttribute((const void*)conv_mma<false>,
                         cudaFuncAttributeMaxDynamicSharedMemorySize, SMEM_BYTES);
    cudaFuncSetAttribute((const void*)conv_mma<true>,
                         cudaFuncAttributeMaxDynamicSharedMemorySize, SMEM_BYTES);

    prep_w<<<64, 512>>>(pw1_w, pw2_w, wt, stats);

    conv_mma<false><<<512, 512, SMEM_BYTES>>>(x, dw1_w, wt, nullptr, nullptr,
                                              y1, stats, stats + CCH);
    bn_finalize<<<1, CCH>>>(stats, stats + CCH, gamma1, beta1, sc, sc + CCH);

    conv_mma<true><<<512, 512, SMEM_BYTES>>>(y1, dw2_w, wt + 65536, sc, sc + CCH,
                                             out, stats + 2 * CCH, stats + 3 * CCH);
    bn_finalize<<<1, CCH>>>(stats + 2 * CCH, stats + 3 * CCH, gamma2, beta2,
                            sc + 2 * CCH, sc + 3 * CCH);

    bn_apply<<<2048, 256>>>(out, sc + 2 * CCH, sc + 3 * CCH);
}

// round 10
// speedup vs baseline: 2.9262x; 1.0812x over previous
#include <cuda_runtime.h>
#include <cuda_fp16.h>
#include <cstdint>

// ---------------- problem constants ----------------
#define NN 32
#define CCH 128
#define HH 64
#define WW 64
#define NHW_F 131072.0f
#define EPSV 1e-5f

// ---------------- smem layout (byte offsets) ----------------
#define TSTRIDE 272                 // 17x16B segs -> LDSM conflict-free
#define WHI_OFF 0
#define THI_OFF 34816               // 128*272
#define XS0_OFF 43520               // + 32*272
// XS: 32 channels x 10 rows x 24 floats (halo col h at offset h+3, cols 1..16 16B-aligned)
#define XROW 24
#define XCH  240
#define XSBUF_BYTES (32 * XCH * 4)          // 30720
#define XS1_OFF (XS0_OFF + XSBUF_BYTES)     // 74240
#define RED_OFF (XS1_OFF + XSBUF_BYTES)     // 104960
#define SMEM_BYTES (RED_OFF + 4096)         // 109056

// ---------------- device scratch ----------------
__device__ float g_y1[NN * CCH * HH * WW];
__device__ unsigned char g_wt[65536];       // 2 blocks x 32KB fp16 [o][c]
__device__ float g_stats[4 * CCH];
__device__ float g_sc[4 * CCH];

// ---------------- PTX helpers ----------------
__device__ __forceinline__ uint32_t smem_u32(const void* p) {
    uint32_t a;
    asm("{ .reg .u64 t; cvta.to.shared.u64 t, %1; cvt.u32.u64 %0, t; }" : "=r"(a) : "l"(p));
    return a;
}
__device__ __forceinline__ void ldsm_x4(uint32_t* r, uint32_t a) {
    asm volatile("ldmatrix.sync.aligned.m8n8.x4.shared.b16 {%0,%1,%2,%3}, [%4];"
                 : "=r"(r[0]), "=r"(r[1]), "=r"(r[2]), "=r"(r[3]) : "r"(a));
}
__device__ __forceinline__ void ldsmt_x4(uint32_t* r, uint32_t a) {
    asm volatile("ldmatrix.sync.aligned.m8n8.x4.trans.shared.b16 {%0,%1,%2,%3}, [%4];"
                 : "=r"(r[0]), "=r"(r[1]), "=r"(r[2]), "=r"(r[3]) : "r"(a));
}
__device__ __forceinline__ void mma16816h(float* d, const uint32_t* a, const uint32_t* b) {
    asm volatile("mma.sync.aligned.m16n8k16.row.col.f32.f16.f16.f32 "
                 "{%0,%1,%2,%3}, {%4,%5,%6,%7}, {%8,%9}, {%0,%1,%2,%3};"
                 : "+f"(d[0]), "+f"(d[1]), "+f"(d[2]), "+f"(d[3])
                 : "r"(a[0]), "r"(a[1]), "r"(a[2]), "r"(a[3]), "r"(b[0]), "r"(b[1]));
}
__device__ __forceinline__ void cp_async4(uint32_t dst, const void* src, uint32_t srcsz) {
    asm volatile("cp.async.ca.shared.global [%0], [%1], 4, %2;"
                 :: "r"(dst), "l"(src), "r"(srcsz) : "memory");
}
__device__ __forceinline__ void cp_async16(uint32_t dst, const void* src, uint32_t srcsz) {
    asm volatile("cp.async.cg.shared.global [%0], [%1], 16, %2;"
                 :: "r"(dst), "l"(src), "r"(srcsz) : "memory");
}
#define CP_COMMIT() asm volatile("cp.async.commit_group;" ::: "memory")
#define CP_WAIT1()  asm volatile("cp.async.wait_group 1;" ::: "memory")
#define CP_WAIT0()  asm volatile("cp.async.wait_group 0;" ::: "memory")

// ---------------- prep: pw weights to fp16; zero stats ----------------
__global__ void prep_w(const float* __restrict__ pw1, const float* __restrict__ pw2,
                       unsigned char* __restrict__ wt, float* __restrict__ stats) {
    int idx = blockIdx.x * blockDim.x + threadIdx.x;
    if (idx < 4 * CCH) stats[idx] = 0.f;
    if (idx >= 32768) return;
    int blk = idx >> 14;
    int w = idx & 16383;
    float v = (blk ? pw2 : pw1)[w];
    *(__half*)(wt + (uint32_t)blk * 32768u + (uint32_t)w * 2u) = __float2half_rn(v);
}

// ---------------- fused relu(+BN) -> dw3x3 -> HMMA(fp16) pointwise + stats ----------------
// 512 CTAs x 512 threads; each CTA: 2 tiles x 4 chunk-stages, cp.async pipelined.
template <bool PRE_BN>
__global__ __launch_bounds__(512, 1) void conv_mma(
    const float* __restrict__ in, const float* __restrict__ dww,
    const unsigned char* __restrict__ wt,
    const float* __restrict__ prescale, const float* __restrict__ preshift,
    float* __restrict__ out, float* __restrict__ osum, float* __restrict__ osq)
{
    extern __shared__ char smb[];
    const uint32_t base32 = smem_u32(smb);

    const int tid = threadIdx.x;
    const int wid = tid >> 5;
    const int lane = tid & 31;
    const int n = blockIdx.x >> 4;
    const int sub = blockIdx.x & 15;

    // ---- halo issue for stage s (tile = sub*2 + (s>>2), chunk = s&3) ----
    auto issue_halo = [&](int s) {
        const int tile = sub * 2 + (s >> 2);
        const int th0 = (tile >> 2) * 8;
        const int tw0 = (tile & 3) * 16;
        const int c0 = (s & 3) * 32;
        const uint32_t xsb = base32 + ((s & 1) ? XS1_OFF : XS0_OFF);
        // vector part: 32ch * 10r * 4 = 1280 16B copies
        #pragma unroll
        for (int u = 0; u < 3; u++) {
            int i = tid + u * 512;
            if (i < 1280) {
                int c = i / 40, rr = i - c * 40;
                int r = rr >> 2, f = rr & 3;
                int gh = th0 - 1 + r;
                bool ok = (unsigned)gh < (unsigned)HH;
                int ghc = ok ? gh : 0;
                const float* src = in + (((size_t)(n * CCH + c0 + c) * HH + ghc) * WW
                                         + tw0 + 4 * f);
                cp_async16(xsb + (uint32_t)(c * XCH + r * XROW + 4 + 4 * f) * 4u,
                           src, ok ? 16u : 0u);
            }
        }
        // scalar part: edge cols h=0 (off 3) and h=17 (off 20): 640 copies
        #pragma unroll
        for (int u = 0; u < 2; u++) {
            int e = tid + u * 512;
            if (e < 640) {
                int c = e / 20, rr = e - c * 20;
                int r = rr >> 1, side = rr & 1;
                int gh = th0 - 1 + r;
                int gw = side ? (tw0 + 16) : (tw0 - 1);
                bool ok = ((unsigned)gh < (unsigned)HH) && ((unsigned)gw < (unsigned)WW);
                const float* src = ok ? in + (((size_t)(n * CCH + c0 + c) * HH + gh) * WW + gw)
                                      : in;
                cp_async4(xsb + (uint32_t)(c * XCH + r * XROW + (side ? 20 : 3)) * 4u,
                          src, ok ? 4u : 0u);
            }
        }
        CP_COMMIT();
    };

    issue_halo(0);

    // ---- W copy into padded smem (vectorized; overlaps stage-0 cp.async) ----
    {
        const float4* whi = (const float4*)wt;     // 2048 f4
        #pragma unroll
        for (int u = 0; u < 4; u++) {
            int i = tid + u * 512;                 // < 2048
            int o = i >> 4, seg = i & 15;
            uint32_t off = (uint32_t)o * TSTRIDE + (uint32_t)seg * 16u;
            *(float4*)(smb + WHI_OFF + off) = whi[i];
        }
    }

    // ---- preload per-chunk BN scale/shift for this thread's dw channel ----
    const int cl = tid >> 4;           // local channel 0..31
    const int m = tid & 15;
    const int ph = m >> 1, half = m & 1;
    float scs[4], shs[4];
    if (PRE_BN) {
        #pragma unroll
        for (int ch = 0; ch < 4; ch++) {
            scs[ch] = prescale[ch * 32 + cl];
            shs[ch] = preshift[ch * 32 + cl];
        }
    }

    // GEMM per-warp tiling: 32(o) x 32(px)
    const int o0 = (wid & 3) * 32;
    const int p0 = (wid >> 2) * 32;
    const uint32_t aRow = (uint32_t)(o0 + (lane & 15)) * TSTRIDE + (uint32_t)(lane >> 4) * 16u;
    const uint32_t bRow = (uint32_t)(lane & 15) * TSTRIDE + (uint32_t)(p0 + (lane >> 4) * 8) * 2u;
    const uint32_t aHi0 = base32 + WHI_OFF + aRow;
    const uint32_t bHi0 = base32 + THI_OFF + bRow;

    float d[2][4][4];
    #pragma unroll
    for (int i = 0; i < 2; i++)
        #pragma unroll
        for (int j = 0; j < 4; j++)
            #pragma unroll
            for (int r = 0; r < 4; r++) d[i][j][r] = 0.f;

    for (int s = 0; s < 8; s++) {
        const int tile = sub * 2 + (s >> 2);
        const int th0 = (tile >> 2) * 8;
        const int tw0 = (tile & 3) * 16;
        const int ch = s & 3;
        const int c0 = ch * 32;
        float* xs = (float*)(smb + ((s & 1) ? XS1_OFF : XS0_OFF));

        if (s < 7) issue_halo(s + 1);
        if (s < 7) { CP_WAIT1(); } else { CP_WAIT0(); }
        __syncthreads();   // stage-s halo arrived; all warps past MMA(s-1)

        // ---- depthwise 3x3 with fused relu(+BN) on register loads ----
        {
            const float* wp = dww + (c0 + cl) * 9;
            float w0 = wp[0], w1 = wp[1], w2 = wp[2], w3 = wp[3], w4 = wp[4],
                  w5 = wp[5], w6 = wp[6], w7 = wp[7], w8 = wp[8];
            const float scv = PRE_BN ? scs[ch] : 1.f;
            const float shv = PRE_BN ? shs[ch] : 0.f;
            const float* xb = xs + cl * XCH + 8 * half;
            float sacc[8];
            #pragma unroll
            for (int j = 0; j < 8; j++) sacc[j] = 0.f;
            #pragma unroll
            for (int r = 0; r < 3; r++) {
                const int gh = th0 - 1 + ph + r;
                const bool rowok = (unsigned)gh < (unsigned)HH;
                if (PRE_BN && !rowok) continue;     // whole row contributes zero
                const float* rp = xb + (ph + r) * XROW;
                float4 A = *(const float4*)(rp);
                float4 B = *(const float4*)(rp + 4);
                float4 C = *(const float4*)(rp + 8);
                float4 D = *(const float4*)(rp + 12);
                float L[16] = {A.x, A.y, A.z, A.w, B.x, B.y, B.z, B.w,
                               C.x, C.y, C.z, C.w, D.x, D.y, D.z, D.w};
                if (PRE_BN) {
                    #pragma unroll
                    for (int j = 0; j < 16; j++)
                        L[j] = fmaxf(fmaf(L[j], scv, shv), 0.f);
                    if (half == 0 && tw0 == 0) L[3] = 0.f;      // left border col
                    if (half == 1 && tw0 == 48) L[12] = 0.f;    // right border col
                } else {
                    #pragma unroll
                    for (int j = 0; j < 16; j++)
                        L[j] = fmaxf(L[j], 0.f);                // zfill OOB stays 0
                }
                float wr0 = (r == 0) ? w0 : (r == 1) ? w3 : w6;
                float wr1 = (r == 0) ? w1 : (r == 1) ? w4 : w7;
                float wr2 = (r == 0) ? w2 : (r == 1) ? w5 : w8;
                #pragma unroll
                for (int j = 0; j < 8; j++)
                    sacc[j] = fmaf(wr0, L[3 + j],
                              fmaf(wr1, L[4 + j],
                              fmaf(wr2, L[5 + j], sacc[j])));
            }
            uint32_t hiw[4];
            #pragma unroll
            for (int jp = 0; jp < 4; jp++) {
                __half h0 = __float2half_rn(sacc[2 * jp]);
                __half h1 = __float2half_rn(sacc[2 * jp + 1]);
                hiw[jp] = (uint32_t)__half_as_ushort(h0)
                        | ((uint32_t)__half_as_ushort(h1) << 16);
            }
            uint32_t toff = (uint32_t)cl * TSTRIDE + (uint32_t)(32 * ph + 16 * half);
            *(uint4*)(smb + THI_OFF + toff) = make_uint4(hiw[0], hiw[1], hiw[2], hiw[3]);
        }
        __syncthreads();   // T(ch) ready

        // ---- MMA for this chunk: 2 k-steps, single W product ----
        #pragma unroll
        for (int kk2 = 0; kk2 < 2; kk2++) {
            const uint32_t ao = (uint32_t)(ch * 2 + kk2) * 32u;
            const uint32_t bo = (uint32_t)kk2 * (16u * TSTRIDE);
            uint32_t ah[2][4], bh[2][4];
            ldsm_x4(ah[0], aHi0 + ao);
            ldsm_x4(ah[1], aHi0 + ao + 16u * TSTRIDE);
            ldsmt_x4(bh[0], bHi0 + bo);
            ldsmt_x4(bh[1], bHi0 + bo + 32u);
            #pragma unroll
            for (int i = 0; i < 2; i++) {
                #pragma unroll
                for (int j = 0; j < 4; j++) {
                    const uint32_t* bhf = &bh[j >> 1][(j & 1) * 2];
                    mma16816h(d[i][j], ah[i], bhf);
                }
            }
        }

        // ---- epilogue after last chunk of the tile ----
        if (ch == 3) {
            const int grp = lane >> 2, tg = lane & 3;
            float* redS = (float*)(smb + RED_OFF);       // 512 floats
            float* redQ = redS + 512;
            #pragma unroll
            for (int i = 0; i < 2; i++) {
                #pragma unroll
                for (int rh = 0; rh < 2; rh++) {
                    int o = o0 + i * 16 + grp + rh * 8;
                    float sv = 0.f, qv = 0.f;
                    #pragma unroll
                    for (int j = 0; j < 4; j++) {
                        int px = p0 + j * 8 + tg * 2;
                        float v0 = d[i][j][rh * 2], v1 = d[i][j][rh * 2 + 1];
                        *(float2*)(out + ((size_t)(n * CCH + o) * HH + th0 + (px >> 4)) * WW
                                         + tw0 + (px & 15)) = make_float2(v0, v1);
                        sv += v0 + v1;
                        qv = fmaf(v0, v0, fmaf(v1, v1, qv));
                    }
                    sv += __shfl_xor_sync(0xffffffffu, sv, 1);
                    sv += __shfl_xor_sync(0xffffffffu, sv, 2);
                    qv += __shfl_xor_sync(0xffffffffu, qv, 1);
                    qv += __shfl_xor_sync(0xffffffffu, qv, 2);
                    if (tg == 0) {
                        redS[o * 4 + (wid >> 2)] = sv;
                        redQ[o * 4 + (wid >> 2)] = qv;
                    }
                }
            }
            // full accumulator reset
            #pragma unroll
            for (int i = 0; i < 2; i++)
                #pragma unroll
                for (int j = 0; j < 4; j++)
                    #pragma unroll
                    for (int r = 0; r < 4; r++) d[i][j][r] = 0.f;
            __syncthreads();
            if (tid < CCH) {
                atomicAdd(&osum[tid], redS[tid * 4] + redS[tid * 4 + 1]
                                    + redS[tid * 4 + 2] + redS[tid * 4 + 3]);
                atomicAdd(&osq[tid], redQ[tid * 4] + redQ[tid * 4 + 1]
                                   + redQ[tid * 4 + 2] + redQ[tid * 4 + 3]);
            }
        }
    }
}

// ---------------- BN helpers ----------------
__global__ void bn_finalize(const float* __restrict__ sum, const float* __restrict__ sq,
                            const float* __restrict__ gamma, const float* __restrict__ beta,
                            float* __restrict__ scale, float* __restrict__ shift) {
    int c = threadIdx.x;
    float inv = 1.0f / NHW_F;
    float m = sum[c] * inv;
    float v = sq[c] * inv - m * m;
    float sc = gamma[c] * rsqrtf(v + EPSV);
    scale[c] = sc;
    shift[c] = beta[c] - m * sc;
}

__global__ void bn_apply(float* __restrict__ y, const float* __restrict__ scale,
                         const float* __restrict__ shift) {
    const int total4 = (NN * CCH * HH * WW) / 4;
    float4* p = (float4*)y;
    for (int i = blockIdx.x * blockDim.x + threadIdx.x; i < total4;
         i += gridDim.x * blockDim.x) {
        int c = (i >> 10) & (CCH - 1);
        float s = scale[c], t = shift[c];
        float4 v = p[i];
        v.x = fmaf(v.x, s, t); v.y = fmaf(v.y, s, t);
        v.z = fmaf(v.z, s, t); v.w = fmaf(v.w, s, t);
        p[i] = v;
    }
}

// ---------------- launch ----------------
extern "C" void kernel_launch(void* const* d_in, const int* in_sizes, int n_in,
                              void* d_out, int out_size) {
    const float* x      = (const float*)d_in[0];
    const float* dw1_w  = (const float*)d_in[1];
    const float* pw1_w  = (const float*)d_in[2];
    const float* gamma1 = (const float*)d_in[3];
    const float* beta1  = (const float*)d_in[4];
    const float* dw2_w  = (const float*)d_in[5];
    const float* pw2_w  = (const float*)d_in[6];
    const float* gamma2 = (const float*)d_in[7];
    const float* beta2  = (const float*)d_in[8];
    float* out = (float*)d_out;

    float *y1, *stats, *sc;
    unsigned char* wt;
    cudaGetSymbolAddress((void**)&y1, g_y1);
    cudaGetSymbolAddress((void**)&stats, g_stats);
    cudaGetSymbolAddress((void**)&sc, g_sc);
    cudaGetSymbolAddress((void**)&wt, g_wt);

    cudaFuncSetAttribute((const void*)conv_mma<false>,
                         cudaFuncAttributeMaxDynamicSharedMemorySize, SMEM_BYTES);
    cudaFuncSetAttribute((const void*)conv_mma<true>,
                         cudaFuncAttributeMaxDynamicSharedMemorySize, SMEM_BYTES);

    prep_w<<<64, 512>>>(pw1_w, pw2_w, wt, stats);

    conv_mma<false><<<512, 512, SMEM_BYTES>>>(x, dw1_w, wt, nullptr, nullptr,
                                              y1, stats, stats + CCH);
    bn_finalize<<<1, CCH>>>(stats, stats + CCH, gamma1, beta1, sc, sc + CCH);

    conv_mma<true><<<512, 512, SMEM_BYTES>>>(y1, dw2_w, wt + 32768, sc, sc + CCH,
                                             out, stats + 2 * CCH, stats + 3 * CCH);
    bn_finalize<<<1, CCH>>>(stats + 2 * CCH, stats + 3 * CCH, gamma2, beta2,
                            sc + 2 * CCH, sc + 3 * CCH);

    bn_apply<<<2048, 256>>>(out, sc + 2 * CCH, sc + 3 * CCH);
}